// round 15
// baseline (speedup 1.0000x reference)
#include <cuda_runtime.h>
#include <cuda_bf16.h>
#include <math.h>
#include <stdint.h>

#define HID     512
#define HH      256
#define G3      768
#define BATCH   16
#define NSENT   16
#define LW      128
#define NSEQW   256
#define MW      32768
#define WSLOT   (768 * 512)

__device__ float g_xpw[2UL * MW * G3];
__device__ float g_sent[NSEQW * HID];
__device__ float g_xps[2 * BATCH * NSENT * G3];
__device__ float g_scw[MW];
__device__ float g_scs[BATCH * NSENT];
__device__ float g_hw[2 * 2 * HH * NSEQW];
__device__ float g_hs[2 * 2 * HH * BATCH];
__device__ unsigned g_flagw[16 * 8];     // per-block step flags (monotonic)
__device__ unsigned g_flags_s[2 * 8];
__device__ __nv_bfloat16 g_Ahi[(size_t)MW * HID];
__device__ __nv_bfloat16 g_Alo[(size_t)MW * HID];
__device__ __nv_bfloat16 g_Whi[6 * WSLOT];
__device__ __nv_bfloat16 g_Wlo[6 * WSLOT];

__device__ __forceinline__ uint32_t smem_u32(const void* p) {
    uint32_t a;
    asm("{ .reg .u64 t; cvta.to.shared.u64 t, %1; cvt.u32.u64 %0, t; }" : "=r"(a) : "l"(p));
    return a;
}
__device__ __forceinline__ void ldsm4(uint32_t* r, uint32_t addr) {
    asm volatile("ldmatrix.sync.aligned.m8n8.x4.shared.b16 {%0,%1,%2,%3}, [%4];"
                 : "=r"(r[0]), "=r"(r[1]), "=r"(r[2]), "=r"(r[3]) : "r"(addr));
}
__device__ __forceinline__ void mma_bf16(float* c, const uint32_t* a, const uint32_t* b) {
    asm volatile("mma.sync.aligned.m16n8k16.row.col.f32.bf16.bf16.f32 "
                 "{%0,%1,%2,%3}, {%4,%5,%6,%7}, {%8,%9}, {%0,%1,%2,%3};"
                 : "+f"(c[0]), "+f"(c[1]), "+f"(c[2]), "+f"(c[3])
                 : "r"(a[0]), "r"(a[1]), "r"(a[2]), "r"(a[3]), "r"(b[0]), "r"(b[1]));
}

// fast gate functions (__expf: ~2 ulp; negligible vs bf16x3 4e-5)
__device__ __forceinline__ float fsigmoid(float x) {
    return 1.f / (1.f + __expf(-x));
}
__device__ __forceinline__ float ftanh_(float x) {
    float e = __expf(-2.f * x);
    return (1.f - e) / (1.f + e);
}

__device__ __forceinline__ void split4(float4 v, __nv_bfloat162* h, __nv_bfloat162* l) {
    float x[4] = {v.x, v.y, v.z, v.w};
    __nv_bfloat16 hh[4], ll[4];
#pragma unroll
    for (int i = 0; i < 4; i++) {
        hh[i] = __float2bfloat16_rn(x[i]);
        ll[i] = __float2bfloat16_rn(x[i] - __bfloat162float(hh[i]));
    }
    h[0] = __nv_bfloat162(hh[0], hh[1]); h[1] = __nv_bfloat162(hh[2], hh[3]);
    l[0] = __nv_bfloat162(ll[0], ll[1]); l[1] = __nv_bfloat162(ll[2], ll[3]);
}

__device__ __forceinline__ void split8(float4 a, float4 b, uint4& hi4, uint4& lo4) {
    __nv_bfloat162 h[2], l[2];
    split4(a, h, l);
    hi4.x = *(uint32_t*)&h[0]; hi4.y = *(uint32_t*)&h[1];
    lo4.x = *(uint32_t*)&l[0]; lo4.y = *(uint32_t*)&l[1];
    split4(b, h, l);
    hi4.z = *(uint32_t*)&h[0]; hi4.w = *(uint32_t*)&h[1];
    lo4.z = *(uint32_t*)&l[0]; lo4.w = *(uint32_t*)&l[1];
}

__global__ void conv_split(const float4* __restrict__ src,
                           __nv_bfloat16* __restrict__ hi,
                           __nv_bfloat16* __restrict__ lo, int n4) {
    int i = blockIdx.x * blockDim.x + threadIdx.x;
    if (i >= n4) return;
    __nv_bfloat162 h[2], l[2];
    split4(src[i], h, l);
    ((__nv_bfloat162*)hi)[2 * i] = h[0]; ((__nv_bfloat162*)hi)[2 * i + 1] = h[1];
    ((__nv_bfloat162*)lo)[2 * i] = l[0]; ((__nv_bfloat162*)lo)[2 * i + 1] = l[1];
}

__global__ void conv_split_gather(const float4* __restrict__ tf,
                                  __nv_bfloat16* __restrict__ hi,
                                  __nv_bfloat16* __restrict__ lo) {
    int i = blockIdx.x * blockDim.x + threadIdx.x;
    if (i >= MW * 128) return;
    int m = i >> 7, kq = i & 127;
    float4 v = tf[((size_t)((m & 2047) * 16 + (m >> 11))) * 128 + kq];
    __nv_bfloat162 h[2], l[2];
    split4(v, h, l);
    ((__nv_bfloat162*)hi)[2 * i] = h[0]; ((__nv_bfloat162*)hi)[2 * i + 1] = h[1];
    ((__nv_bfloat162*)lo)[2 * i] = l[0]; ((__nv_bfloat162*)lo)[2 * i + 1] = l[1];
}

__global__ void zero_scores(float* a, int na, float* b, int nb) {
    int i = blockIdx.x * blockDim.x + threadIdx.x;
    if (i < na) a[i] = 0.f;
    if (i < nb) b[i] = 0.f;
}

// MODE 0: C[m][n] = sum_k A[m][k]*B[n][k] + bias[n]
// MODE 1: C[m] += sum_n tanh(acc + bias[n]) * ctx[n]
#define GEMM_SMEM 131072
template<int MODE>
__global__ void __launch_bounds__(256, 1)
gemm_tc(const __nv_bfloat16* __restrict__ Ahi, const __nv_bfloat16* __restrict__ Alo,
        const __nv_bfloat16* __restrict__ Bhi, const __nv_bfloat16* __restrict__ Blo,
        const float* __restrict__ bias, float* __restrict__ C, int ldc,
        const float* __restrict__ ctx)
{
    extern __shared__ __align__(128) char smg[];
    const uint32_t sb = smem_u32(smg);
    const int tid = threadIdx.x;
    const int lane = tid & 31, wid = tid >> 5;
    const int wm = wid >> 2, wn = wid & 3;
    const int m0 = blockIdx.y * 128, n0 = blockIdx.x * 128;

    const __nv_bfloat16* planes[4] = {
        Ahi + (size_t)m0 * 512, Alo + (size_t)m0 * 512,
        Bhi + (size_t)n0 * 512, Blo + (size_t)n0 * 512 };

    const int rb = lane & 7;
    const int glA = lane >> 4;
    const int glB = lane >> 3;
    int aoff[4], boff[4];
#pragma unroll
    for (int mt = 0; mt < 4; mt++) {
        int r = wm * 64 + mt * 16 + rb + ((lane >> 3) & 1) * 8;
        aoff[mt] = ((r >> 3) << 10) + (rb << 7);
    }
#pragma unroll
    for (int nt = 0; nt < 4; nt++) {
        int r = wn * 32 + nt * 8 + rb;
        boff[nt] = ((r >> 3) << 10) + (rb << 7);
    }

    float acc[4][4][4];
#pragma unroll
    for (int a = 0; a < 4; a++)
#pragma unroll
        for (int b = 0; b < 4; b++)
#pragma unroll
            for (int d = 0; d < 4; d++) acc[a][b][d] = 0.f;

    const int ldg = tid & 7;
    const int ldr = tid >> 3;

#pragma unroll
    for (int i = 0; i < 16; i++) {
        const int pl = i >> 2;
        const int r = ((i & 3) << 5) + ldr;
        const __nv_bfloat16* src = planes[pl] + (size_t)r * 512 + ldg * 8;
        uint32_t dst = sb + pl * 16384 + ((r >> 3) << 10) + ((r & 7) << 7)
                       + ((ldg ^ (r & 7)) << 4);
        asm volatile("cp.async.cg.shared.global [%0], [%1], 16;" :: "r"(dst), "l"(src));
    }
    asm volatile("cp.async.commit_group;" ::: "memory");

    for (int c = 0; c < 8; c++) {
        asm volatile("cp.async.wait_group 0;" ::: "memory");
        __syncthreads();
        if (c < 7) {
            const int k0 = (c + 1) << 6;
            const uint32_t dbase = sb + ((c + 1) & 1) * 65536;
#pragma unroll
            for (int i = 0; i < 16; i++) {
                const int pl = i >> 2;
                const int r = ((i & 3) << 5) + ldr;
                const __nv_bfloat16* src = planes[pl] + (size_t)r * 512 + k0 + ldg * 8;
                uint32_t dst = dbase + pl * 16384 + ((r >> 3) << 10) + ((r & 7) << 7)
                               + ((ldg ^ (r & 7)) << 4);
                asm volatile("cp.async.cg.shared.global [%0], [%1], 16;" :: "r"(dst), "l"(src));
            }
            asm volatile("cp.async.commit_group;" ::: "memory");
        }

        const uint32_t bbase = sb + (c & 1) * 65536;
        uint32_t Bf[2][4][4];
#pragma unroll
        for (int s = 0; s < 4; s++) {
            if ((s & 1) == 0) {
                const int q0 = s << 1;
#pragma unroll
                for (int pl = 0; pl < 2; pl++)
#pragma unroll
                    for (int nt = 0; nt < 4; nt++)
                        ldsm4(Bf[pl][nt],
                              bbase + (2 + pl) * 16384 + boff[nt]
                              + (((q0 + glB) ^ rb) << 4));
            }
            uint32_t Af[2][4][4];
#pragma unroll
            for (int pl = 0; pl < 2; pl++)
#pragma unroll
                for (int mt = 0; mt < 4; mt++)
                    ldsm4(Af[pl][mt],
                          bbase + pl * 16384 + aoff[mt]
                          + ((((s << 1) + glA) ^ rb) << 4));
            const int ro = (s & 1) << 1;
#pragma unroll
            for (int mt = 0; mt < 4; mt++)
#pragma unroll
                for (int nt = 0; nt < 4; nt++) {
                    mma_bf16(acc[mt][nt], Af[0][mt], &Bf[0][nt][ro]);
                    mma_bf16(acc[mt][nt], Af[0][mt], &Bf[1][nt][ro]);
                    mma_bf16(acc[mt][nt], Af[1][mt], &Bf[0][nt][ro]);
                }
        }
    }

    const int rr = lane >> 2, cc = (lane & 3) * 2;
    if (MODE == 0) {
#pragma unroll
        for (int mt = 0; mt < 4; mt++) {
            const int row = m0 + wm * 64 + mt * 16 + rr;
#pragma unroll
            for (int nt = 0; nt < 4; nt++) {
                const int col = n0 + wn * 32 + nt * 8 + cc;
                const float b0 = bias[col], b1 = bias[col + 1];
                float2 v0 = {acc[mt][nt][0] + b0, acc[mt][nt][1] + b1};
                float2 v1 = {acc[mt][nt][2] + b0, acc[mt][nt][3] + b1};
                *(float2*)(C + (size_t)row * ldc + col) = v0;
                *(float2*)(C + (size_t)(row + 8) * ldc + col) = v1;
            }
        }
    } else {
#pragma unroll
        for (int mt = 0; mt < 4; mt++) {
            float s0 = 0.f, s1 = 0.f;
#pragma unroll
            for (int nt = 0; nt < 4; nt++) {
                const int col = n0 + wn * 32 + nt * 8 + cc;
                const float b0 = bias[col], b1 = bias[col + 1];
                const float c0 = ctx[col],  c1 = ctx[col + 1];
                s0 += tanhf(acc[mt][nt][0] + b0) * c0 + tanhf(acc[mt][nt][1] + b1) * c1;
                s1 += tanhf(acc[mt][nt][2] + b0) * c0 + tanhf(acc[mt][nt][3] + b1) * c1;
            }
            s0 += __shfl_xor_sync(0xffffffffu, s0, 1);
            s0 += __shfl_xor_sync(0xffffffffu, s0, 2);
            s1 += __shfl_xor_sync(0xffffffffu, s1, 1);
            s1 += __shfl_xor_sync(0xffffffffu, s1, 2);
            if ((lane & 3) == 0) {
                const int row = m0 + wm * 64 + mt * 16 + rr;
                atomicAdd(C + row, s0);
                atomicAdd(C + row + 8, s1);
            }
        }
    }
}

__device__ __forceinline__ unsigned ld_acq(const unsigned* p) {
    unsigned v;
    asm volatile("ld.acquire.gpu.u32 %0, [%1];" : "=r"(v) : "l"(p) : "memory");
    return v;
}
// flag barrier: block bx releases flags[bx] = target; all wait for 8 flags >= target
__device__ __forceinline__ void flag_barrier(unsigned* flags, int bx,
                                             unsigned target) {
    __syncthreads();
    if (threadIdx.x == 0) {
        asm volatile("st.release.gpu.u32 [%0], %1;" :: "l"(flags + bx), "r"(target)
                     : "memory");
        for (;;) {
            unsigned ok = 1;
#pragma unroll
            for (int i = 0; i < 8; i++)
                ok &= (ld_acq(flags + i) >= target) ? 1u : 0u;
            if (ok) break;
        }
    }
    __syncthreads();
}

// word GRU on tensor cores: 3-chain mma accumulators, fast gates, flag barrier
#define GRUW_SMEM 177920
__global__ void __launch_bounds__(384, 1)
gru_mma(const float* __restrict__ xp_base,
        const float* __restrict__ whh_f, const float* __restrict__ whh_b,
        const float* __restrict__ bhh_f, const float* __restrict__ bhh_b,
        float* __restrict__ hbuf,
        __nv_bfloat16* __restrict__ ohi, __nv_bfloat16* __restrict__ olo,
        unsigned* flag_arr, int nseq)
{
    constexpr int T = LW;
    extern __shared__ __align__(128) char smem[];
    const uint32_t sb = smem_u32(smem);
    const uint32_t WH = 0, WL = 49152, HHp = 98304, HLp = 114688;
    float* hfp = (float*)(smem + 131072);
    float* Csm = (float*)(smem + 164864);
    float* bsm = (float*)(smem + 177536);

    const int tid = threadIdx.x;
    const int lane = tid & 31, wid = tid >> 5;
    const int j0 = blockIdx.x * 32;
    const int sg0 = blockIdx.y * 32;
    const int dir = blockIdx.z;
    unsigned* flags = flag_arr + (dir * gridDim.y + blockIdx.y) * 8;
    const float* whh = dir ? whh_b : whh_f;
    const float* bhh = dir ? bhh_b : bhh_f;
    const float* xp  = xp_base + (size_t)dir * nseq * T * G3;

    for (int task = tid; task < 96 * 32; task += 384) {
        int row = task >> 5, c = task & 31;
        int grow = (row >> 5) * 256 + j0 + (row & 31);
        const float* src = whh + (size_t)grow * 256 + c * 8;
        float4 v0 = *(const float4*)src;
        float4 v1 = *(const float4*)(src + 4);
        uint4 hi4, lo4;
        split8(v0, v1, hi4, lo4);
        uint32_t off = row * 512 + ((c ^ (row & 7)) << 4);
        *(uint4*)(smem + WH + off) = hi4;
        *(uint4*)(smem + WL + off) = lo4;
    }
    for (int i = tid; i < 96; i += 384)
        bsm[i] = bhh[(i >> 5) * 256 + j0 + (i & 31)];

    const unsigned base = flags[blockIdx.x];   // monotonic, all equal at entry
    const int wm = wid >> 1;
    const int np = wid & 1;
    const int rb = lane & 7;
    const int glA = lane >> 4;
    const int glB = lane >> 3;
    const uint32_t arow = (uint32_t)(wm * 16 + rb + ((lane >> 3) & 1) * 8) * 512;
    const int rr = lane >> 2, cc = (lane & 3) * 2;

    float xr_[3], xz_[3], xn_[3];
    {
        const int tt0 = dir ? (T - 1) : 0;
#pragma unroll
        for (int k = 0; k < 3; k++) {
            int p = tid + k * 384;
            if (p < 1024) {
                int seq = p >> 5, jj = p & 31;
                const float* row = xp + ((size_t)(sg0 + seq) * T + tt0) * G3;
                xr_[k] = row[j0 + jj];
                xz_[k] = row[256 + j0 + jj];
                xn_[k] = row[512 + j0 + jj];
            }
        }
    }
    __syncthreads();

    for (int step = 0; step < T; step++) {
        const int tt = dir ? (T - 1 - step) : step;

        // phase 1: stage/convert h(t)
        if (step == 0) {
            for (int e = tid; e < 2048; e += 384)
                *(uint4*)(smem + HHp + e * 16) = make_uint4(0, 0, 0, 0);
            for (int e = tid; e < 32 * 264; e += 384) hfp[e] = 0.f;
        } else {
            const float* hcur = hbuf + ((size_t)((step & 1) * 2 + dir)) * nseq * 256
                                + (size_t)sg0 * 256;
            for (int task = tid; task < 1024; task += 384) {
                int row = task >> 5, c = task & 31;
                const float* src = hcur + row * 256 + c * 8;
                float4 v0 = *(const float4*)src;
                float4 v1 = *(const float4*)(src + 4);
                uint4 hi4, lo4;
                split8(v0, v1, hi4, lo4);
                uint32_t off = row * 512 + ((c ^ (row & 7)) << 4);
                *(uint4*)(smem + HHp + off) = hi4;
                *(uint4*)(smem + HLp + off) = lo4;
                *(float4*)(hfp + row * 264 + c * 8) = v0;
                *(float4*)(hfp + row * 264 + c * 8 + 4) = v1;
            }
        }
        __syncthreads();

        // phase 2: mma C[96 x 32] = W * h^T, 3 independent plane chains
        {
            float acc[3][2][4];
#pragma unroll
            for (int pchain = 0; pchain < 3; pchain++)
#pragma unroll
                for (int t = 0; t < 2; t++)
#pragma unroll
                    for (int d = 0; d < 4; d++) acc[pchain][t][d] = 0.f;
            uint32_t Bf[2][2][4];
#pragma unroll
            for (int s = 0; s < 16; s++) {
                if ((s & 1) == 0) {
                    const int q0 = s << 1;
#pragma unroll
                    for (int pl = 0; pl < 2; pl++)
#pragma unroll
                        for (int t = 0; t < 2; t++) {
                            uint32_t brow = (uint32_t)((np * 2 + t) * 8 + rb) * 512;
                            ldsm4(Bf[pl][t], sb + (pl ? HLp : HHp) + brow
                                  + (((q0 + glB) ^ rb) << 4));
                        }
                }
                uint32_t Af[2][4];
#pragma unroll
                for (int pl = 0; pl < 2; pl++)
                    ldsm4(Af[pl], sb + (pl ? WL : WH) + arow
                          + ((((s << 1) + glA) ^ rb) << 4));
                const int ro = (s & 1) << 1;
#pragma unroll
                for (int t = 0; t < 2; t++) {
                    mma_bf16(acc[0][t], Af[0], &Bf[0][t][ro]);   // hi*hi
                    mma_bf16(acc[1][t], Af[0], &Bf[1][t][ro]);   // hi*lo
                    mma_bf16(acc[2][t], Af[1], &Bf[0][t][ro]);   // lo*hi
                }
            }
            const int row = wm * 16 + rr;
#pragma unroll
            for (int t = 0; t < 2; t++) {
                const int col = (np * 2 + t) * 8 + cc;
                float d0 = acc[0][t][0] + acc[1][t][0] + acc[2][t][0];
                float d1 = acc[0][t][1] + acc[1][t][1] + acc[2][t][1];
                float d2 = acc[0][t][2] + acc[1][t][2] + acc[2][t][2];
                float d3 = acc[0][t][3] + acc[1][t][3] + acc[2][t][3];
                Csm[row * 33 + col]           = d0;
                Csm[row * 33 + col + 1]       = d1;
                Csm[(row + 8) * 33 + col]     = d2;
                Csm[(row + 8) * 33 + col + 1] = d3;
            }
        }
        __syncthreads();

        // phase 3: fast gates; store h(t+1) + bf16 planes directly
        float* hnext = hbuf + ((size_t)(((step + 1) & 1) * 2 + dir)) * nseq * 256
                       + (size_t)sg0 * 256;
        const bool notlast = (step < T - 1);
#pragma unroll
        for (int k = 0; k < 3; k++) {
            int p = tid + k * 384;
            if (p < 1024) {
                int seq = p >> 5, jj = p & 31;
                float sR = Csm[jj * 33 + seq];
                float sZ = Csm[(32 + jj) * 33 + seq];
                float sN = Csm[(64 + jj) * 33 + seq];
                float hold = hfp[seq * 264 + j0 + jj];
                float r  = fsigmoid(xr_[k] + sR + bsm[jj]);
                float z  = fsigmoid(xz_[k] + sZ + bsm[32 + jj]);
                float nn = ftanh_(xn_[k] + r * (sN + bsm[64 + jj]));
                float hnew = (1.f - z) * nn + z * hold;
                if (notlast) hnext[seq * 256 + j0 + jj] = hnew;
                size_t oidx = ((size_t)(sg0 + seq) * T + tt) * HID + dir * HH + j0 + jj;
                __nv_bfloat16 hb = __float2bfloat16_rn(hnew);
                ohi[oidx] = hb;
                olo[oidx] = __float2bfloat16_rn(hnew - __bfloat162float(hb));
            }
        }

        if (notlast) {
            const int t2 = dir ? (T - 2 - step) : (step + 1);
            // prefetch next xp before the barrier wait
            float nxr[3], nxz[3], nxn[3];
#pragma unroll
            for (int k = 0; k < 3; k++) {
                int p = tid + k * 384;
                if (p < 1024) {
                    int seq = p >> 5, jj = p & 31;
                    const float* row = xp + ((size_t)(sg0 + seq) * T + t2) * G3;
                    nxr[k] = row[j0 + jj];
                    nxz[k] = row[256 + j0 + jj];
                    nxn[k] = row[512 + j0 + jj];
                }
            }
#pragma unroll
            for (int k = 0; k < 3; k++) { xr_[k] = nxr[k]; xz_[k] = nxz[k]; xn_[k] = nxn[k]; }
            flag_barrier(flags, blockIdx.x, base + (unsigned)step + 1u);
        }
    }
}

// sentence GRU: R8 butterfly + fast gates + flag barrier
template<int T, int SPB>
__global__ void __launch_bounds__(512, 1)
gru_reg(const float* __restrict__ xp_base,
        const float* __restrict__ whh_f, const float* __restrict__ whh_b,
        const float* __restrict__ bhh_f, const float* __restrict__ bhh_b,
        float* __restrict__ hbuf,
        __nv_bfloat16* __restrict__ ohi, __nv_bfloat16* __restrict__ olo,
        unsigned* flag_arr, int nseq)
{
    constexpr int NQ = SPB / 8;
    constexpr int HROW = 320;
    __shared__ __align__(16) float hsm[SPB * HROW];
    __shared__ float xs[32 * (SPB + 1)];

    const int tid = threadIdx.x;
    const int jj = tid >> 4;
    const int ks = tid & 15;
    const int j0 = blockIdx.x * 32;
    const int sg0 = blockIdx.y * SPB;
    const int dir = blockIdx.z;
    unsigned* flags = flag_arr + (blockIdx.z * gridDim.y + blockIdx.y) * 8;
    const float* whh = dir ? whh_b : whh_f;
    const float* bhh = dir ? bhh_b : bhh_f;
    const float* xp  = xp_base + (size_t)dir * nseq * T * G3;
    const int j = j0 + jj;

    unsigned long long Wp[3][8];
#pragma unroll
    for (int g = 0; g < 3; g++)
#pragma unroll
        for (int p = 0; p < 4; p++) {
            float4 v = *(const float4*)(whh + ((size_t)(g * 256 + j)) * 256
                                        + ks * 16 + p * 4);
            asm("mov.b64 %0, {%1,%2};" : "=l"(Wp[g][2*p])     : "f"(v.x), "f"(v.y));
            asm("mov.b64 %0, {%1,%2};" : "=l"(Wp[g][2*p + 1]) : "f"(v.z), "f"(v.w));
        }

    const float br = bhh[j], bz = bhh[256 + j], bn = bhh[512 + j];
    const uint32_t hbase = smem_u32(hsm);
    const unsigned base = flags[blockIdx.x];
    const bool own = (ks < 8);
    const bool b0 = (ks & 1), b1 = ((ks >> 1) & 1), b2 = ((ks >> 2) & 1);

    float xr_[NQ], xz_[NQ], xn_[NQ];
    if (own) {
        const int tt = dir ? (T - 1) : 0;
#pragma unroll
        for (int q = 0; q < NQ; q++) {
            const float* row = xp + ((size_t)(sg0 + q * 8 + ks) * T + tt) * G3;
            xr_[q] = row[j]; xz_[q] = row[256 + j]; xn_[q] = row[512 + j];
        }
    }

    for (int step = 0; step < T; step++) {
        const int tt = dir ? (T - 1 - step) : step;

        if (step == 0) {
            for (int e = tid; e < SPB * HROW; e += 512) hsm[e] = 0.f;
        } else {
            const float4* hcur4 = (const float4*)(hbuf
                + ((size_t)((step & 1) * 2 + dir)) * nseq * 256 + (size_t)sg0 * 256);
#pragma unroll
            for (int i = 0; i < SPB / 8; i++) {
                int e = tid + i * 512;
                int s = e >> 6, c4 = e & 63;
                float4 v = hcur4[e];
                *(float4*)(hsm + s * HROW + (c4 >> 2) * 20 + (c4 & 3) * 4) = v;
            }
        }
        __syncthreads();

#pragma unroll
        for (int q = 0; q < NQ; q++) {
            float v3[3][8];
#pragma unroll
            for (int s8 = 0; s8 < 8; s8++) {
                const int s = q * 8 + s8;
                const uint32_t ha = hbase + (uint32_t)(s * HROW) * 4 + ks * 80;
                unsigned long long a0 = 0ULL, a1 = 0ULL, a2 = 0ULL;
#pragma unroll
                for (int p = 0; p < 4; p++) {
                    unsigned long long h0, h1;
                    asm("ld.shared.v2.b64 {%0,%1}, [%2];"
                        : "=l"(h0), "=l"(h1) : "r"(ha + p * 16));
                    asm("fma.rn.f32x2 %0, %1, %2, %0;" : "+l"(a0) : "l"(Wp[0][2*p]),   "l"(h0));
                    asm("fma.rn.f32x2 %0, %1, %2, %0;" : "+l"(a1) : "l"(Wp[1][2*p]),   "l"(h0));
                    asm("fma.rn.f32x2 %0, %1, %2, %0;" : "+l"(a2) : "l"(Wp[2][2*p]),   "l"(h0));
                    asm("fma.rn.f32x2 %0, %1, %2, %0;" : "+l"(a0) : "l"(Wp[0][2*p+1]), "l"(h1));
                    asm("fma.rn.f32x2 %0, %1, %2, %0;" : "+l"(a1) : "l"(Wp[1][2*p+1]), "l"(h1));
                    asm("fma.rn.f32x2 %0, %1, %2, %0;" : "+l"(a2) : "l"(Wp[2][2*p+1]), "l"(h1));
                }
                float lo, hi;
                asm("mov.b64 {%0,%1}, %2;" : "=f"(lo), "=f"(hi) : "l"(a0)); v3[0][s8] = lo + hi;
                asm("mov.b64 {%0,%1}, %2;" : "=f"(lo), "=f"(hi) : "l"(a1)); v3[1][s8] = lo + hi;
                asm("mov.b64 {%0,%1}, %2;" : "=f"(lo), "=f"(hi) : "l"(a2)); v3[2][s8] = lo + hi;
            }

            float sv[3];
#pragma unroll
            for (int g = 0; g < 3; g++) {
                float t0[4], t1[2];
#pragma unroll
                for (int i = 0; i < 4; i++) {
                    float keep = b0 ? v3[g][2*i + 1] : v3[g][2*i];
                    float send = b0 ? v3[g][2*i]     : v3[g][2*i + 1];
                    t0[i] = keep + __shfl_xor_sync(0xffffffffu, send, 1);
                }
#pragma unroll
                for (int i = 0; i < 2; i++) {
                    float keep = b1 ? t0[2*i + 1] : t0[2*i];
                    float send = b1 ? t0[2*i]     : t0[2*i + 1];
                    t1[i] = keep + __shfl_xor_sync(0xffffffffu, send, 2);
                }
                float keep = b2 ? t1[1] : t1[0];
                float send = b2 ? t1[0] : t1[1];
                float r = keep + __shfl_xor_sync(0xffffffffu, send, 4);
                r += __shfl_xor_sync(0xffffffffu, r, 8);
                sv[g] = r;
            }

            if (own) {
                const int s = q * 8 + ks;
                const float hold = hsm[s * HROW + (j >> 4) * 20 + (j & 15)];
                const float r  = fsigmoid(xr_[q] + sv[0] + br);
                const float z  = fsigmoid(xz_[q] + sv[1] + bz);
                const float nn = ftanh_(xn_[q] + r * (sv[2] + bn));
                const float hnew = (1.f - z) * nn + z * hold;
                xs[jj * (SPB + 1) + s] = hnew;
                size_t oidx = ((size_t)(sg0 + s) * T + tt) * HID + dir * HH + j;
                __nv_bfloat16 hb = __float2bfloat16_rn(hnew);
                ohi[oidx] = hb;
                olo[oidx] = __float2bfloat16_rn(hnew - __bfloat162float(hb));
            }
        }
        __syncthreads();

        if (step < T - 1) {
            float* hnext = hbuf + ((size_t)(((step + 1) & 1) * 2 + dir)) * nseq * 256
                           + (size_t)sg0 * 256;
#pragma unroll
            for (int e = tid; e < SPB * 32; e += 512) {
                int s = e >> 5, jr = e & 31;
                hnext[s * 256 + j0 + jr] = xs[jr * (SPB + 1) + s];
            }
            const int t2 = dir ? (T - 2 - step) : (step + 1);
            if (own) {
#pragma unroll
                for (int q = 0; q < NQ; q++) {
                    const float* row = xp + ((size_t)(sg0 + q * 8 + ks) * T + t2) * G3;
                    xr_[q] = row[j]; xz_[q] = row[256 + j]; xn_[q] = row[512 + j];
                }
            }
            flag_barrier(flags, blockIdx.x, base + (unsigned)step + 1u);
        }
    }
}

// attention reduce from scores; feats reconstructed from bf16 hi/lo planes
__global__ __launch_bounds__(256)
void attn_reduce2(const float* __restrict__ scores,
                  const __nv_bfloat16* __restrict__ fhi,
                  const __nv_bfloat16* __restrict__ flo,
                  float* __restrict__ dst,
                  int T)
{
    const int seq = blockIdx.x;
    const int tid = threadIdx.x;
    __shared__ float ssc[128];
    __shared__ float sred[256];

    float v = (tid < T) ? scores[seq * T + tid] : -1e30f;
    sred[tid] = v; __syncthreads();
    for (int o = 128; o; o >>= 1) { if (tid < o) sred[tid] = fmaxf(sred[tid], sred[tid + o]); __syncthreads(); }
    float mx = sred[0]; __syncthreads();
    float e = (tid < T) ? expf(v - mx) : 0.f;
    sred[tid] = e; __syncthreads();
    for (int o = 128; o; o >>= 1) { if (tid < o) sred[tid] += sred[tid + o]; __syncthreads(); }
    float inv = 1.f / sred[0]; __syncthreads();
    if (tid < T) ssc[tid] = e * inv;
    __syncthreads();

    const __nv_bfloat162* h2 = (const __nv_bfloat162*)fhi;
    const __nv_bfloat162* l2 = (const __nv_bfloat162*)flo;
    float a0 = 0.f, a1 = 0.f;
    for (int t = 0; t < T; t++) {
        const size_t base2 = ((size_t)seq * T + t) * 256 + tid;
        __nv_bfloat162 hv = h2[base2];
        __nv_bfloat162 lv = l2[base2];
        float w = ssc[t];
        a0 = fmaf(w, __bfloat162float(hv.x) + __bfloat162float(lv.x), a0);
        a1 = fmaf(w, __bfloat162float(hv.y) + __bfloat162float(lv.y), a1);
    }
    dst[(size_t)seq * 512 + 2 * tid]     = a0;
    dst[(size_t)seq * 512 + 2 * tid + 1] = a1;
}

extern "C" void kernel_launch(void* const* d_in, const int* in_sizes, int n_in,
                              void* d_out, int out_size)
{
    const float* tf       = (const float*)d_in[0];
    const float* w_wih_f  = (const float*)d_in[2];
    const float* w_whh_f  = (const float*)d_in[3];
    const float* w_bih_f  = (const float*)d_in[4];
    const float* w_bhh_f  = (const float*)d_in[5];
    const float* w_wih_b  = (const float*)d_in[6];
    const float* w_whh_b  = (const float*)d_in[7];
    const float* w_bih_b  = (const float*)d_in[8];
    const float* w_bhh_b  = (const float*)d_in[9];
    const float* s_wih_f  = (const float*)d_in[10];
    const float* s_whh_f  = (const float*)d_in[11];
    const float* s_bih_f  = (const float*)d_in[12];
    const float* s_bhh_f  = (const float*)d_in[13];
    const float* s_wih_b  = (const float*)d_in[14];
    const float* s_whh_b  = (const float*)d_in[15];
    const float* s_bih_b  = (const float*)d_in[16];
    const float* s_bhh_b  = (const float*)d_in[17];
    const float* w_attn_w = (const float*)d_in[18];
    const float* w_attn_b = (const float*)d_in[19];
    const float* w_ctx    = (const float*)d_in[20];
    const float* s_attn_w = (const float*)d_in[21];
    const float* s_attn_b = (const float*)d_in[22];
    const float* s_ctx    = (const float*)d_in[23];

    float *xpw, *sent, *xps, *hw, *hs, *scw, *scs;
    unsigned *fw, *fs;
    __nv_bfloat16 *Ahi, *Alo, *Whi, *Wlo;
    cudaGetSymbolAddress((void**)&xpw,  g_xpw);
    cudaGetSymbolAddress((void**)&sent, g_sent);
    cudaGetSymbolAddress((void**)&xps,  g_xps);
    cudaGetSymbolAddress((void**)&scw,  g_scw);
    cudaGetSymbolAddress((void**)&scs,  g_scs);
    cudaGetSymbolAddress((void**)&hw,   g_hw);
    cudaGetSymbolAddress((void**)&hs,   g_hs);
    cudaGetSymbolAddress((void**)&fw,   g_flagw);
    cudaGetSymbolAddress((void**)&fs,   g_flags_s);
    cudaGetSymbolAddress((void**)&Ahi,  g_Ahi);
    cudaGetSymbolAddress((void**)&Alo,  g_Alo);
    cudaGetSymbolAddress((void**)&Whi,  g_Whi);
    cudaGetSymbolAddress((void**)&Wlo,  g_Wlo);

    cudaFuncSetAttribute(gemm_tc<0>,
                         cudaFuncAttributeMaxDynamicSharedMemorySize, GEMM_SMEM);
    cudaFuncSetAttribute(gemm_tc<1>,
                         cudaFuncAttributeMaxDynamicSharedMemorySize, GEMM_SMEM);
    cudaFuncSetAttribute(gru_mma,
                         cudaFuncAttributeMaxDynamicSharedMemorySize, GRUW_SMEM);

    const float* wsrc[6] = {w_wih_f, w_wih_b, w_attn_w, s_wih_f, s_wih_b, s_attn_w};
    const int    wrows[6] = {768, 768, 512, 768, 768, 512};
    auto wsplit = [&](int i) {
        int n4 = wrows[i] * 128;
        conv_split<<<(n4 + 255) / 256, 256>>>((const float4*)wsrc[i],
                                              Whi + (size_t)i * WSLOT,
                                              Wlo + (size_t)i * WSLOT, n4);
    };

    zero_scores<<<(MW + 255) / 256, 256>>>(scw, MW, scs, BATCH * NSENT);

    wsplit(0); wsplit(1);
    conv_split_gather<<<(MW * 128 + 255) / 256, 256>>>((const float4*)tf, Ahi, Alo);
    {
        dim3 g(6, 256);
        gemm_tc<0><<<g, 256, GEMM_SMEM>>>(Ahi, Alo, Whi, Wlo, w_bih_f, xpw, G3, nullptr);
        gemm_tc<0><<<g, 256, GEMM_SMEM>>>(Ahi, Alo, Whi + WSLOT, Wlo + WSLOT, w_bih_b,
                                          xpw + (size_t)MW * G3, G3, nullptr);
    }
    // word BiGRU (tensor-core step; emits bf16 planes into Ahi/Alo)
    {
        dim3 g(8, 8, 2);
        gru_mma<<<g, 384, GRUW_SMEM>>>(xpw, w_whh_f, w_whh_b, w_bhh_f, w_bhh_b,
                                       hw, Ahi, Alo, fw, NSEQW);
    }

    // word attention: score-fused GEMM + reduce
    wsplit(2);
    {
        dim3 g(4, 256);
        gemm_tc<1><<<g, 256, GEMM_SMEM>>>(Ahi, Alo, Whi + 2 * WSLOT, Wlo + 2 * WSLOT,
                                          w_attn_b, scw, 0, w_ctx);
        attn_reduce2<<<NSEQW, 256>>>(scw, Ahi, Alo, sent, LW);
    }

    // sentence input-gate GEMMs
    wsplit(3); wsplit(4);
    conv_split<<<(NSEQW * 128 + 255) / 256, 256>>>((const float4*)sent, Ahi, Alo, NSEQW * 128);
    {
        dim3 g(6, 2);
        gemm_tc<0><<<g, 256, GEMM_SMEM>>>(Ahi, Alo, Whi + 3 * WSLOT, Wlo + 3 * WSLOT,
                                          s_bih_f, xps, G3, nullptr);
        gemm_tc<0><<<g, 256, GEMM_SMEM>>>(Ahi, Alo, Whi + 4 * WSLOT, Wlo + 4 * WSLOT,
                                          s_bih_b, xps + (size_t)BATCH * NSENT * G3, G3, nullptr);
    }

    // sentence BiGRU (emits bf16 planes into Ahi/Alo)
    {
        dim3 g(8, 1, 2);
        gru_reg<NSENT, 16><<<g, 512>>>(xps, s_whh_f, s_whh_b, s_bhh_f, s_bhh_b,
                                       hs, Ahi, Alo, fs, BATCH);
    }

    // sentence attention -> output
    wsplit(5);
    {
        dim3 g(4, 2);
        gemm_tc<1><<<g, 256, GEMM_SMEM>>>(Ahi, Alo, Whi + 5 * WSLOT, Wlo + 5 * WSLOT,
                                          s_attn_b, scs, 0, s_ctx);
        attn_reduce2<<<BATCH, 256>>>(scs, Ahi, Alo, (float*)d_out, NSENT);
    }
}

// round 16
// speedup vs baseline: 1.8016x; 1.8016x over previous
#include <cuda_runtime.h>
#include <cuda_bf16.h>
#include <math.h>
#include <stdint.h>

#define HID     512
#define HH      256
#define G3      768
#define BATCH   16
#define NSENT   16
#define LW      128
#define NSEQW   256
#define MW      32768
#define WSLOT   (768 * 512)

__device__ float g_xpw[2UL * MW * G3];
__device__ float g_sent[NSEQW * HID];
__device__ float g_xps[2 * BATCH * NSENT * G3];
__device__ float g_scw[MW];
__device__ float g_scs[BATCH * NSENT];
__device__ float g_hw[2 * 2 * HH * NSEQW];
__device__ float g_hs[2 * 2 * HH * BATCH];
__device__ unsigned g_barw_cnt[16], g_barw_sense[16];
__device__ unsigned g_bars_cnt[2],  g_bars_sense[2];
__device__ __nv_bfloat16 g_Ahi[(size_t)MW * HID];
__device__ __nv_bfloat16 g_Alo[(size_t)MW * HID];
__device__ __nv_bfloat16 g_Whi[6 * WSLOT];
__device__ __nv_bfloat16 g_Wlo[6 * WSLOT];

__device__ __forceinline__ uint32_t smem_u32(const void* p) {
    uint32_t a;
    asm("{ .reg .u64 t; cvta.to.shared.u64 t, %1; cvt.u32.u64 %0, t; }" : "=r"(a) : "l"(p));
    return a;
}
__device__ __forceinline__ void ldsm4(uint32_t* r, uint32_t addr) {
    asm volatile("ldmatrix.sync.aligned.m8n8.x4.shared.b16 {%0,%1,%2,%3}, [%4];"
                 : "=r"(r[0]), "=r"(r[1]), "=r"(r[2]), "=r"(r[3]) : "r"(addr));
}
__device__ __forceinline__ void mma_bf16(float* c, const uint32_t* a, const uint32_t* b) {
    asm volatile("mma.sync.aligned.m16n8k16.row.col.f32.bf16.bf16.f32 "
                 "{%0,%1,%2,%3}, {%4,%5,%6,%7}, {%8,%9}, {%0,%1,%2,%3};"
                 : "+f"(c[0]), "+f"(c[1]), "+f"(c[2]), "+f"(c[3])
                 : "r"(a[0]), "r"(a[1]), "r"(a[2]), "r"(a[3]), "r"(b[0]), "r"(b[1]));
}

// fast gate functions (__expf: ~2 ulp; negligible vs bf16x3 4e-5)
__device__ __forceinline__ float fsigmoid(float x) {
    return 1.f / (1.f + __expf(-x));
}
__device__ __forceinline__ float ftanh_(float x) {
    float e = __expf(-2.f * x);
    return (1.f - e) / (1.f + e);
}

__device__ __forceinline__ void split4(float4 v, __nv_bfloat162* h, __nv_bfloat162* l) {
    float x[4] = {v.x, v.y, v.z, v.w};
    __nv_bfloat16 hh[4], ll[4];
#pragma unroll
    for (int i = 0; i < 4; i++) {
        hh[i] = __float2bfloat16_rn(x[i]);
        ll[i] = __float2bfloat16_rn(x[i] - __bfloat162float(hh[i]));
    }
    h[0] = __nv_bfloat162(hh[0], hh[1]); h[1] = __nv_bfloat162(hh[2], hh[3]);
    l[0] = __nv_bfloat162(ll[0], ll[1]); l[1] = __nv_bfloat162(ll[2], ll[3]);
}

__device__ __forceinline__ void split8(float4 a, float4 b, uint4& hi4, uint4& lo4) {
    __nv_bfloat162 h[2], l[2];
    split4(a, h, l);
    hi4.x = *(uint32_t*)&h[0]; hi4.y = *(uint32_t*)&h[1];
    lo4.x = *(uint32_t*)&l[0]; lo4.y = *(uint32_t*)&l[1];
    split4(b, h, l);
    hi4.z = *(uint32_t*)&h[0]; hi4.w = *(uint32_t*)&h[1];
    lo4.z = *(uint32_t*)&l[0]; lo4.w = *(uint32_t*)&l[1];
}

__global__ void conv_split(const float4* __restrict__ src,
                           __nv_bfloat16* __restrict__ hi,
                           __nv_bfloat16* __restrict__ lo, int n4) {
    int i = blockIdx.x * blockDim.x + threadIdx.x;
    if (i >= n4) return;
    __nv_bfloat162 h[2], l[2];
    split4(src[i], h, l);
    ((__nv_bfloat162*)hi)[2 * i] = h[0]; ((__nv_bfloat162*)hi)[2 * i + 1] = h[1];
    ((__nv_bfloat162*)lo)[2 * i] = l[0]; ((__nv_bfloat162*)lo)[2 * i + 1] = l[1];
}

__global__ void conv_split_gather(const float4* __restrict__ tf,
                                  __nv_bfloat16* __restrict__ hi,
                                  __nv_bfloat16* __restrict__ lo) {
    int i = blockIdx.x * blockDim.x + threadIdx.x;
    if (i >= MW * 128) return;
    int m = i >> 7, kq = i & 127;
    float4 v = tf[((size_t)((m & 2047) * 16 + (m >> 11))) * 128 + kq];
    __nv_bfloat162 h[2], l[2];
    split4(v, h, l);
    ((__nv_bfloat162*)hi)[2 * i] = h[0]; ((__nv_bfloat162*)hi)[2 * i + 1] = h[1];
    ((__nv_bfloat162*)lo)[2 * i] = l[0]; ((__nv_bfloat162*)lo)[2 * i + 1] = l[1];
}

__global__ void zero_scores(float* a, int na, float* b, int nb) {
    int i = blockIdx.x * blockDim.x + threadIdx.x;
    if (i < na) a[i] = 0.f;
    if (i < nb) b[i] = 0.f;
}

// MODE 0: C[m][n] = sum_k A[m][k]*B[n][k] + bias[n]
// MODE 1: C[m] += sum_n tanh(acc + bias[n]) * ctx[n]
#define GEMM_SMEM 131072
template<int MODE>
__global__ void __launch_bounds__(256, 1)
gemm_tc(const __nv_bfloat16* __restrict__ Ahi, const __nv_bfloat16* __restrict__ Alo,
        const __nv_bfloat16* __restrict__ Bhi, const __nv_bfloat16* __restrict__ Blo,
        const float* __restrict__ bias, float* __restrict__ C, int ldc,
        const float* __restrict__ ctx)
{
    extern __shared__ __align__(128) char smg[];
    const uint32_t sb = smem_u32(smg);
    const int tid = threadIdx.x;
    const int lane = tid & 31, wid = tid >> 5;
    const int wm = wid >> 2, wn = wid & 3;
    const int m0 = blockIdx.y * 128, n0 = blockIdx.x * 128;

    const __nv_bfloat16* planes[4] = {
        Ahi + (size_t)m0 * 512, Alo + (size_t)m0 * 512,
        Bhi + (size_t)n0 * 512, Blo + (size_t)n0 * 512 };

    const int rb = lane & 7;
    const int glA = lane >> 4;
    const int glB = lane >> 3;
    int aoff[4], boff[4];
#pragma unroll
    for (int mt = 0; mt < 4; mt++) {
        int r = wm * 64 + mt * 16 + rb + ((lane >> 3) & 1) * 8;
        aoff[mt] = ((r >> 3) << 10) + (rb << 7);
    }
#pragma unroll
    for (int nt = 0; nt < 4; nt++) {
        int r = wn * 32 + nt * 8 + rb;
        boff[nt] = ((r >> 3) << 10) + (rb << 7);
    }

    float acc[4][4][4];
#pragma unroll
    for (int a = 0; a < 4; a++)
#pragma unroll
        for (int b = 0; b < 4; b++)
#pragma unroll
            for (int d = 0; d < 4; d++) acc[a][b][d] = 0.f;

    const int ldg = tid & 7;
    const int ldr = tid >> 3;

#pragma unroll
    for (int i = 0; i < 16; i++) {
        const int pl = i >> 2;
        const int r = ((i & 3) << 5) + ldr;
        const __nv_bfloat16* src = planes[pl] + (size_t)r * 512 + ldg * 8;
        uint32_t dst = sb + pl * 16384 + ((r >> 3) << 10) + ((r & 7) << 7)
                       + ((ldg ^ (r & 7)) << 4);
        asm volatile("cp.async.cg.shared.global [%0], [%1], 16;" :: "r"(dst), "l"(src));
    }
    asm volatile("cp.async.commit_group;" ::: "memory");

    for (int c = 0; c < 8; c++) {
        asm volatile("cp.async.wait_group 0;" ::: "memory");
        __syncthreads();
        if (c < 7) {
            const int k0 = (c + 1) << 6;
            const uint32_t dbase = sb + ((c + 1) & 1) * 65536;
#pragma unroll
            for (int i = 0; i < 16; i++) {
                const int pl = i >> 2;
                const int r = ((i & 3) << 5) + ldr;
                const __nv_bfloat16* src = planes[pl] + (size_t)r * 512 + k0 + ldg * 8;
                uint32_t dst = dbase + pl * 16384 + ((r >> 3) << 10) + ((r & 7) << 7)
                               + ((ldg ^ (r & 7)) << 4);
                asm volatile("cp.async.cg.shared.global [%0], [%1], 16;" :: "r"(dst), "l"(src));
            }
            asm volatile("cp.async.commit_group;" ::: "memory");
        }

        const uint32_t bbase = sb + (c & 1) * 65536;
        uint32_t Bf[2][4][4];
#pragma unroll
        for (int s = 0; s < 4; s++) {
            if ((s & 1) == 0) {
                const int q0 = s << 1;
#pragma unroll
                for (int pl = 0; pl < 2; pl++)
#pragma unroll
                    for (int nt = 0; nt < 4; nt++)
                        ldsm4(Bf[pl][nt],
                              bbase + (2 + pl) * 16384 + boff[nt]
                              + (((q0 + glB) ^ rb) << 4));
            }
            uint32_t Af[2][4][4];
#pragma unroll
            for (int pl = 0; pl < 2; pl++)
#pragma unroll
                for (int mt = 0; mt < 4; mt++)
                    ldsm4(Af[pl][mt],
                          bbase + pl * 16384 + aoff[mt]
                          + ((((s << 1) + glA) ^ rb) << 4));
            const int ro = (s & 1) << 1;
#pragma unroll
            for (int mt = 0; mt < 4; mt++)
#pragma unroll
                for (int nt = 0; nt < 4; nt++) {
                    mma_bf16(acc[mt][nt], Af[0][mt], &Bf[0][nt][ro]);
                    mma_bf16(acc[mt][nt], Af[0][mt], &Bf[1][nt][ro]);
                    mma_bf16(acc[mt][nt], Af[1][mt], &Bf[0][nt][ro]);
                }
        }
    }

    const int rr = lane >> 2, cc = (lane & 3) * 2;
    if (MODE == 0) {
#pragma unroll
        for (int mt = 0; mt < 4; mt++) {
            const int row = m0 + wm * 64 + mt * 16 + rr;
#pragma unroll
            for (int nt = 0; nt < 4; nt++) {
                const int col = n0 + wn * 32 + nt * 8 + cc;
                const float b0 = bias[col], b1 = bias[col + 1];
                float2 v0 = {acc[mt][nt][0] + b0, acc[mt][nt][1] + b1};
                float2 v1 = {acc[mt][nt][2] + b0, acc[mt][nt][3] + b1};
                *(float2*)(C + (size_t)row * ldc + col) = v0;
                *(float2*)(C + (size_t)(row + 8) * ldc + col) = v1;
            }
        }
    } else {
#pragma unroll
        for (int mt = 0; mt < 4; mt++) {
            float s0 = 0.f, s1 = 0.f;
#pragma unroll
            for (int nt = 0; nt < 4; nt++) {
                const int col = n0 + wn * 32 + nt * 8 + cc;
                const float b0 = bias[col], b1 = bias[col + 1];
                const float c0 = ctx[col],  c1 = ctx[col + 1];
                s0 += tanhf(acc[mt][nt][0] + b0) * c0 + tanhf(acc[mt][nt][1] + b1) * c1;
                s1 += tanhf(acc[mt][nt][2] + b0) * c0 + tanhf(acc[mt][nt][3] + b1) * c1;
            }
            s0 += __shfl_xor_sync(0xffffffffu, s0, 1);
            s0 += __shfl_xor_sync(0xffffffffu, s0, 2);
            s1 += __shfl_xor_sync(0xffffffffu, s1, 1);
            s1 += __shfl_xor_sync(0xffffffffu, s1, 2);
            if ((lane & 3) == 0) {
                const int row = m0 + wm * 64 + mt * 16 + rr;
                atomicAdd(C + row, s0);
                atomicAdd(C + row + 8, s1);
            }
        }
    }
}

__device__ __forceinline__ unsigned ld_acq(const unsigned* p) {
    unsigned v;
    asm volatile("ld.acquire.gpu.u32 %0, [%1];" : "=r"(v) : "l"(p) : "memory");
    return v;
}
// R14-proven barrier: single atomic + single-word sense spin
__device__ __forceinline__ void group_barrier(unsigned* cnt, unsigned* sense,
                                              unsigned target, int total) {
    __syncthreads();
    if (threadIdx.x == 0) {
        __threadfence();
        unsigned t = atomicAdd(cnt, 1u);
        if (t == (unsigned)(total - 1)) {
            *cnt = 0u;
            asm volatile("red.release.gpu.add.u32 [%0], 1;" :: "l"(sense) : "memory");
        } else {
            while (ld_acq(sense) != target) { }
        }
    }
    __syncthreads();
}

// word GRU on tensor cores: 3-chain mma accumulators, fast gates, R14 barrier
#define GRUW_SMEM 177920
__global__ void __launch_bounds__(384, 1)
gru_mma(const float* __restrict__ xp_base,
        const float* __restrict__ whh_f, const float* __restrict__ whh_b,
        const float* __restrict__ bhh_f, const float* __restrict__ bhh_b,
        float* __restrict__ hbuf,
        __nv_bfloat16* __restrict__ ohi, __nv_bfloat16* __restrict__ olo,
        unsigned* cnt_arr, unsigned* sense_arr, int nseq)
{
    constexpr int T = LW;
    extern __shared__ __align__(128) char smem[];
    const uint32_t sb = smem_u32(smem);
    const uint32_t WH = 0, WL = 49152, HHp = 98304, HLp = 114688;
    float* hfp = (float*)(smem + 131072);
    float* Csm = (float*)(smem + 164864);
    float* bsm = (float*)(smem + 177536);

    const int tid = threadIdx.x;
    const int lane = tid & 31, wid = tid >> 5;
    const int j0 = blockIdx.x * 32;
    const int sg0 = blockIdx.y * 32;
    const int dir = blockIdx.z;
    const int gidx = dir * gridDim.y + blockIdx.y;
    unsigned* bcnt = cnt_arr + gidx;
    unsigned* bsense = sense_arr + gidx;
    const float* whh = dir ? whh_b : whh_f;
    const float* bhh = dir ? bhh_b : bhh_f;
    const float* xp  = xp_base + (size_t)dir * nseq * T * G3;

    for (int task = tid; task < 96 * 32; task += 384) {
        int row = task >> 5, c = task & 31;
        int grow = (row >> 5) * 256 + j0 + (row & 31);
        const float* src = whh + (size_t)grow * 256 + c * 8;
        float4 v0 = *(const float4*)src;
        float4 v1 = *(const float4*)(src + 4);
        uint4 hi4, lo4;
        split8(v0, v1, hi4, lo4);
        uint32_t off = row * 512 + ((c ^ (row & 7)) << 4);
        *(uint4*)(smem + WH + off) = hi4;
        *(uint4*)(smem + WL + off) = lo4;
    }
    for (int i = tid; i < 96; i += 384)
        bsm[i] = bhh[(i >> 5) * 256 + j0 + (i & 31)];

    const unsigned base = ld_acq(bsense);
    const int wm = wid >> 1;
    const int np = wid & 1;
    const int rb = lane & 7;
    const int glA = lane >> 4;
    const int glB = lane >> 3;
    const uint32_t arow = (uint32_t)(wm * 16 + rb + ((lane >> 3) & 1) * 8) * 512;
    const int rr = lane >> 2, cc = (lane & 3) * 2;

    float xr_[3], xz_[3], xn_[3];
    {
        const int tt0 = dir ? (T - 1) : 0;
#pragma unroll
        for (int k = 0; k < 3; k++) {
            int p = tid + k * 384;
            if (p < 1024) {
                int seq = p >> 5, jj = p & 31;
                const float* row = xp + ((size_t)(sg0 + seq) * T + tt0) * G3;
                xr_[k] = row[j0 + jj];
                xz_[k] = row[256 + j0 + jj];
                xn_[k] = row[512 + j0 + jj];
            }
        }
    }
    __syncthreads();

    for (int step = 0; step < T; step++) {
        const int tt = dir ? (T - 1 - step) : step;

        // phase 1: stage/convert h(t)
        if (step == 0) {
            for (int e = tid; e < 2048; e += 384)
                *(uint4*)(smem + HHp + e * 16) = make_uint4(0, 0, 0, 0);
            for (int e = tid; e < 32 * 264; e += 384) hfp[e] = 0.f;
        } else {
            const float* hcur = hbuf + ((size_t)((step & 1) * 2 + dir)) * nseq * 256
                                + (size_t)sg0 * 256;
            for (int task = tid; task < 1024; task += 384) {
                int row = task >> 5, c = task & 31;
                const float* src = hcur + row * 256 + c * 8;
                float4 v0 = *(const float4*)src;
                float4 v1 = *(const float4*)(src + 4);
                uint4 hi4, lo4;
                split8(v0, v1, hi4, lo4);
                uint32_t off = row * 512 + ((c ^ (row & 7)) << 4);
                *(uint4*)(smem + HHp + off) = hi4;
                *(uint4*)(smem + HLp + off) = lo4;
                *(float4*)(hfp + row * 264 + c * 8) = v0;
                *(float4*)(hfp + row * 264 + c * 8 + 4) = v1;
            }
        }
        __syncthreads();

        // phase 2: mma C[96 x 32] = W * h^T, 3 independent plane chains
        {
            float acc[3][2][4];
#pragma unroll
            for (int pchain = 0; pchain < 3; pchain++)
#pragma unroll
                for (int t = 0; t < 2; t++)
#pragma unroll
                    for (int d = 0; d < 4; d++) acc[pchain][t][d] = 0.f;
            uint32_t Bf[2][2][4];
#pragma unroll
            for (int s = 0; s < 16; s++) {
                if ((s & 1) == 0) {
                    const int q0 = s << 1;
#pragma unroll
                    for (int pl = 0; pl < 2; pl++)
#pragma unroll
                        for (int t = 0; t < 2; t++) {
                            uint32_t brow = (uint32_t)((np * 2 + t) * 8 + rb) * 512;
                            ldsm4(Bf[pl][t], sb + (pl ? HLp : HHp) + brow
                                  + (((q0 + glB) ^ rb) << 4));
                        }
                }
                uint32_t Af[2][4];
#pragma unroll
                for (int pl = 0; pl < 2; pl++)
                    ldsm4(Af[pl], sb + (pl ? WL : WH) + arow
                          + ((((s << 1) + glA) ^ rb) << 4));
                const int ro = (s & 1) << 1;
#pragma unroll
                for (int t = 0; t < 2; t++) {
                    mma_bf16(acc[0][t], Af[0], &Bf[0][t][ro]);   // hi*hi
                    mma_bf16(acc[1][t], Af[0], &Bf[1][t][ro]);   // hi*lo
                    mma_bf16(acc[2][t], Af[1], &Bf[0][t][ro]);   // lo*hi
                }
            }
            const int row = wm * 16 + rr;
#pragma unroll
            for (int t = 0; t < 2; t++) {
                const int col = (np * 2 + t) * 8 + cc;
                Csm[row * 33 + col]           = acc[0][t][0] + acc[1][t][0] + acc[2][t][0];
                Csm[row * 33 + col + 1]       = acc[0][t][1] + acc[1][t][1] + acc[2][t][1];
                Csm[(row + 8) * 33 + col]     = acc[0][t][2] + acc[1][t][2] + acc[2][t][2];
                Csm[(row + 8) * 33 + col + 1] = acc[0][t][3] + acc[1][t][3] + acc[2][t][3];
            }
        }
        __syncthreads();

        // phase 3: fast gates; store h(t+1) + bf16 planes directly
        float* hnext = hbuf + ((size_t)(((step + 1) & 1) * 2 + dir)) * nseq * 256
                       + (size_t)sg0 * 256;
        const bool notlast = (step < T - 1);
#pragma unroll
        for (int k = 0; k < 3; k++) {
            int p = tid + k * 384;
            if (p < 1024) {
                int seq = p >> 5, jj = p & 31;
                float sR = Csm[jj * 33 + seq];
                float sZ = Csm[(32 + jj) * 33 + seq];
                float sN = Csm[(64 + jj) * 33 + seq];
                float hold = hfp[seq * 264 + j0 + jj];
                float r  = fsigmoid(xr_[k] + sR + bsm[jj]);
                float z  = fsigmoid(xz_[k] + sZ + bsm[32 + jj]);
                float nn = ftanh_(xn_[k] + r * (sN + bsm[64 + jj]));
                float hnew = (1.f - z) * nn + z * hold;
                if (notlast) hnext[seq * 256 + j0 + jj] = hnew;
                size_t oidx = ((size_t)(sg0 + seq) * T + tt) * HID + dir * HH + j0 + jj;
                __nv_bfloat16 hb = __float2bfloat16_rn(hnew);
                ohi[oidx] = hb;
                olo[oidx] = __float2bfloat16_rn(hnew - __bfloat162float(hb));
            }
        }

        if (notlast) {
            const int t2 = dir ? (T - 2 - step) : (step + 1);
#pragma unroll
            for (int k = 0; k < 3; k++) {
                int p = tid + k * 384;
                if (p < 1024) {
                    int seq = p >> 5, jj = p & 31;
                    const float* row = xp + ((size_t)(sg0 + seq) * T + t2) * G3;
                    xr_[k] = row[j0 + jj];
                    xz_[k] = row[256 + j0 + jj];
                    xn_[k] = row[512 + j0 + jj];
                }
            }
            group_barrier(bcnt, bsense, base + (unsigned)step + 1u, 8);
        }
    }
}

// sentence GRU: R8 butterfly + fast gates + R14 barrier
template<int T, int SPB>
__global__ void __launch_bounds__(512, 1)
gru_reg(const float* __restrict__ xp_base,
        const float* __restrict__ whh_f, const float* __restrict__ whh_b,
        const float* __restrict__ bhh_f, const float* __restrict__ bhh_b,
        float* __restrict__ hbuf,
        __nv_bfloat16* __restrict__ ohi, __nv_bfloat16* __restrict__ olo,
        unsigned* cnt_arr, unsigned* sense_arr, int nseq)
{
    constexpr int NQ = SPB / 8;
    constexpr int HROW = 320;
    __shared__ __align__(16) float hsm[SPB * HROW];
    __shared__ float xs[32 * (SPB + 1)];

    const int tid = threadIdx.x;
    const int jj = tid >> 4;
    const int ks = tid & 15;
    const int j0 = blockIdx.x * 32;
    const int sg0 = blockIdx.y * SPB;
    const int dir = blockIdx.z;
    const int gidx = blockIdx.z * gridDim.y + blockIdx.y;
    unsigned* bcnt = cnt_arr + gidx;
    unsigned* bsense = sense_arr + gidx;
    const float* whh = dir ? whh_b : whh_f;
    const float* bhh = dir ? bhh_b : bhh_f;
    const float* xp  = xp_base + (size_t)dir * nseq * T * G3;
    const int j = j0 + jj;

    unsigned long long Wp[3][8];
#pragma unroll
    for (int g = 0; g < 3; g++)
#pragma unroll
        for (int p = 0; p < 4; p++) {
            float4 v = *(const float4*)(whh + ((size_t)(g * 256 + j)) * 256
                                        + ks * 16 + p * 4);
            asm("mov.b64 %0, {%1,%2};" : "=l"(Wp[g][2*p])     : "f"(v.x), "f"(v.y));
            asm("mov.b64 %0, {%1,%2};" : "=l"(Wp[g][2*p + 1]) : "f"(v.z), "f"(v.w));
        }

    const float br = bhh[j], bz = bhh[256 + j], bn = bhh[512 + j];
    const uint32_t hbase = smem_u32(hsm);
    const unsigned base = ld_acq(bsense);
    const bool own = (ks < 8);
    const bool b0 = (ks & 1), b1 = ((ks >> 1) & 1), b2 = ((ks >> 2) & 1);

    float xr_[NQ], xz_[NQ], xn_[NQ];
    if (own) {
        const int tt = dir ? (T - 1) : 0;
#pragma unroll
        for (int q = 0; q < NQ; q++) {
            const float* row = xp + ((size_t)(sg0 + q * 8 + ks) * T + tt) * G3;
            xr_[q] = row[j]; xz_[q] = row[256 + j]; xn_[q] = row[512 + j];
        }
    }

    for (int step = 0; step < T; step++) {
        const int tt = dir ? (T - 1 - step) : step;

        if (step == 0) {
            for (int e = tid; e < SPB * HROW; e += 512) hsm[e] = 0.f;
        } else {
            const float4* hcur4 = (const float4*)(hbuf
                + ((size_t)((step & 1) * 2 + dir)) * nseq * 256 + (size_t)sg0 * 256);
#pragma unroll
            for (int i = 0; i < SPB / 8; i++) {
                int e = tid + i * 512;
                int s = e >> 6, c4 = e & 63;
                float4 v = hcur4[e];
                *(float4*)(hsm + s * HROW + (c4 >> 2) * 20 + (c4 & 3) * 4) = v;
            }
        }
        __syncthreads();

#pragma unroll
        for (int q = 0; q < NQ; q++) {
            float v3[3][8];
#pragma unroll
            for (int s8 = 0; s8 < 8; s8++) {
                const int s = q * 8 + s8;
                const uint32_t ha = hbase + (uint32_t)(s * HROW) * 4 + ks * 80;
                unsigned long long a0 = 0ULL, a1 = 0ULL, a2 = 0ULL;
#pragma unroll
                for (int p = 0; p < 4; p++) {
                    unsigned long long h0, h1;
                    asm("ld.shared.v2.b64 {%0,%1}, [%2];"
                        : "=l"(h0), "=l"(h1) : "r"(ha + p * 16));
                    asm("fma.rn.f32x2 %0, %1, %2, %0;" : "+l"(a0) : "l"(Wp[0][2*p]),   "l"(h0));
                    asm("fma.rn.f32x2 %0, %1, %2, %0;" : "+l"(a1) : "l"(Wp[1][2*p]),   "l"(h0));
                    asm("fma.rn.f32x2 %0, %1, %2, %0;" : "+l"(a2) : "l"(Wp[2][2*p]),   "l"(h0));
                    asm("fma.rn.f32x2 %0, %1, %2, %0;" : "+l"(a0) : "l"(Wp[0][2*p+1]), "l"(h1));
                    asm("fma.rn.f32x2 %0, %1, %2, %0;" : "+l"(a1) : "l"(Wp[1][2*p+1]), "l"(h1));
                    asm("fma.rn.f32x2 %0, %1, %2, %0;" : "+l"(a2) : "l"(Wp[2][2*p+1]), "l"(h1));
                }
                float lo, hi;
                asm("mov.b64 {%0,%1}, %2;" : "=f"(lo), "=f"(hi) : "l"(a0)); v3[0][s8] = lo + hi;
                asm("mov.b64 {%0,%1}, %2;" : "=f"(lo), "=f"(hi) : "l"(a1)); v3[1][s8] = lo + hi;
                asm("mov.b64 {%0,%1}, %2;" : "=f"(lo), "=f"(hi) : "l"(a2)); v3[2][s8] = lo + hi;
            }

            float sv[3];
#pragma unroll
            for (int g = 0; g < 3; g++) {
                float t0[4], t1[2];
#pragma unroll
                for (int i = 0; i < 4; i++) {
                    float keep = b0 ? v3[g][2*i + 1] : v3[g][2*i];
                    float send = b0 ? v3[g][2*i]     : v3[g][2*i + 1];
                    t0[i] = keep + __shfl_xor_sync(0xffffffffu, send, 1);
                }
#pragma unroll
                for (int i = 0; i < 2; i++) {
                    float keep = b1 ? t0[2*i + 1] : t0[2*i];
                    float send = b1 ? t0[2*i]     : t0[2*i + 1];
                    t1[i] = keep + __shfl_xor_sync(0xffffffffu, send, 2);
                }
                float keep = b2 ? t1[1] : t1[0];
                float send = b2 ? t1[0] : t1[1];
                float r = keep + __shfl_xor_sync(0xffffffffu, send, 4);
                r += __shfl_xor_sync(0xffffffffu, r, 8);
                sv[g] = r;
            }

            if (own) {
                const int s = q * 8 + ks;
                const float hold = hsm[s * HROW + (j >> 4) * 20 + (j & 15)];
                const float r  = fsigmoid(xr_[q] + sv[0] + br);
                const float z  = fsigmoid(xz_[q] + sv[1] + bz);
                const float nn = ftanh_(xn_[q] + r * (sv[2] + bn));
                const float hnew = (1.f - z) * nn + z * hold;
                xs[jj * (SPB + 1) + s] = hnew;
                size_t oidx = ((size_t)(sg0 + s) * T + tt) * HID + dir * HH + j;
                __nv_bfloat16 hb = __float2bfloat16_rn(hnew);
                ohi[oidx] = hb;
                olo[oidx] = __float2bfloat16_rn(hnew - __bfloat162float(hb));
            }
        }
        __syncthreads();

        if (step < T - 1) {
            float* hnext = hbuf + ((size_t)(((step + 1) & 1) * 2 + dir)) * nseq * 256
                           + (size_t)sg0 * 256;
#pragma unroll
            for (int e = tid; e < SPB * 32; e += 512) {
                int s = e >> 5, jr = e & 31;
                hnext[s * 256 + j0 + jr] = xs[jr * (SPB + 1) + s];
            }
            const int t2 = dir ? (T - 2 - step) : (step + 1);
            if (own) {
#pragma unroll
                for (int q = 0; q < NQ; q++) {
                    const float* row = xp + ((size_t)(sg0 + q * 8 + ks) * T + t2) * G3;
                    xr_[q] = row[j]; xz_[q] = row[256 + j]; xn_[q] = row[512 + j];
                }
            }
            group_barrier(bcnt, bsense, base + (unsigned)step + 1u, 8);
        }
    }
}

// attention reduce from scores; feats reconstructed from bf16 hi/lo planes
__global__ __launch_bounds__(256)
void attn_reduce2(const float* __restrict__ scores,
                  const __nv_bfloat16* __restrict__ fhi,
                  const __nv_bfloat16* __restrict__ flo,
                  float* __restrict__ dst,
                  int T)
{
    const int seq = blockIdx.x;
    const int tid = threadIdx.x;
    __shared__ float ssc[128];
    __shared__ float sred[256];

    float v = (tid < T) ? scores[seq * T + tid] : -1e30f;
    sred[tid] = v; __syncthreads();
    for (int o = 128; o; o >>= 1) { if (tid < o) sred[tid] = fmaxf(sred[tid], sred[tid + o]); __syncthreads(); }
    float mx = sred[0]; __syncthreads();
    float e = (tid < T) ? expf(v - mx) : 0.f;
    sred[tid] = e; __syncthreads();
    for (int o = 128; o; o >>= 1) { if (tid < o) sred[tid] += sred[tid + o]; __syncthreads(); }
    float inv = 1.f / sred[0]; __syncthreads();
    if (tid < T) ssc[tid] = e * inv;
    __syncthreads();

    const __nv_bfloat162* h2 = (const __nv_bfloat162*)fhi;
    const __nv_bfloat162* l2 = (const __nv_bfloat162*)flo;
    float a0 = 0.f, a1 = 0.f;
    for (int t = 0; t < T; t++) {
        const size_t base2 = ((size_t)seq * T + t) * 256 + tid;
        __nv_bfloat162 hv = h2[base2];
        __nv_bfloat162 lv = l2[base2];
        float w = ssc[t];
        a0 = fmaf(w, __bfloat162float(hv.x) + __bfloat162float(lv.x), a0);
        a1 = fmaf(w, __bfloat162float(hv.y) + __bfloat162float(lv.y), a1);
    }
    dst[(size_t)seq * 512 + 2 * tid]     = a0;
    dst[(size_t)seq * 512 + 2 * tid + 1] = a1;
}

extern "C" void kernel_launch(void* const* d_in, const int* in_sizes, int n_in,
                              void* d_out, int out_size)
{
    const float* tf       = (const float*)d_in[0];
    const float* w_wih_f  = (const float*)d_in[2];
    const float* w_whh_f  = (const float*)d_in[3];
    const float* w_bih_f  = (const float*)d_in[4];
    const float* w_bhh_f  = (const float*)d_in[5];
    const float* w_wih_b  = (const float*)d_in[6];
    const float* w_whh_b  = (const float*)d_in[7];
    const float* w_bih_b  = (const float*)d_in[8];
    const float* w_bhh_b  = (const float*)d_in[9];
    const float* s_wih_f  = (const float*)d_in[10];
    const float* s_whh_f  = (const float*)d_in[11];
    const float* s_bih_f  = (const float*)d_in[12];
    const float* s_bhh_f  = (const float*)d_in[13];
    const float* s_wih_b  = (const float*)d_in[14];
    const float* s_whh_b  = (const float*)d_in[15];
    const float* s_bih_b  = (const float*)d_in[16];
    const float* s_bhh_b  = (const float*)d_in[17];
    const float* w_attn_w = (const float*)d_in[18];
    const float* w_attn_b = (const float*)d_in[19];
    const float* w_ctx    = (const float*)d_in[20];
    const float* s_attn_w = (const float*)d_in[21];
    const float* s_attn_b = (const float*)d_in[22];
    const float* s_ctx    = (const float*)d_in[23];

    float *xpw, *sent, *xps, *hw, *hs, *scw, *scs;
    unsigned *bwc, *bws, *bsc, *bss;
    __nv_bfloat16 *Ahi, *Alo, *Whi, *Wlo;
    cudaGetSymbolAddress((void**)&xpw,  g_xpw);
    cudaGetSymbolAddress((void**)&sent, g_sent);
    cudaGetSymbolAddress((void**)&xps,  g_xps);
    cudaGetSymbolAddress((void**)&scw,  g_scw);
    cudaGetSymbolAddress((void**)&scs,  g_scs);
    cudaGetSymbolAddress((void**)&hw,   g_hw);
    cudaGetSymbolAddress((void**)&hs,   g_hs);
    cudaGetSymbolAddress((void**)&bwc,  g_barw_cnt);
    cudaGetSymbolAddress((void**)&bws,  g_barw_sense);
    cudaGetSymbolAddress((void**)&bsc,  g_bars_cnt);
    cudaGetSymbolAddress((void**)&bss,  g_bars_sense);
    cudaGetSymbolAddress((void**)&Ahi,  g_Ahi);
    cudaGetSymbolAddress((void**)&Alo,  g_Alo);
    cudaGetSymbolAddress((void**)&Whi,  g_Whi);
    cudaGetSymbolAddress((void**)&Wlo,  g_Wlo);

    cudaFuncSetAttribute(gemm_tc<0>,
                         cudaFuncAttributeMaxDynamicSharedMemorySize, GEMM_SMEM);
    cudaFuncSetAttribute(gemm_tc<1>,
                         cudaFuncAttributeMaxDynamicSharedMemorySize, GEMM_SMEM);
    cudaFuncSetAttribute(gru_mma,
                         cudaFuncAttributeMaxDynamicSharedMemorySize, GRUW_SMEM);

    const float* wsrc[6] = {w_wih_f, w_wih_b, w_attn_w, s_wih_f, s_wih_b, s_attn_w};
    const int    wrows[6] = {768, 768, 512, 768, 768, 512};
    auto wsplit = [&](int i) {
        int n4 = wrows[i] * 128;
        conv_split<<<(n4 + 255) / 256, 256>>>((const float4*)wsrc[i],
                                              Whi + (size_t)i * WSLOT,
                                              Wlo + (size_t)i * WSLOT, n4);
    };

    zero_scores<<<(MW + 255) / 256, 256>>>(scw, MW, scs, BATCH * NSENT);

    wsplit(0); wsplit(1);
    conv_split_gather<<<(MW * 128 + 255) / 256, 256>>>((const float4*)tf, Ahi, Alo);
    {
        dim3 g(6, 256);
        gemm_tc<0><<<g, 256, GEMM_SMEM>>>(Ahi, Alo, Whi, Wlo, w_bih_f, xpw, G3, nullptr);
        gemm_tc<0><<<g, 256, GEMM_SMEM>>>(Ahi, Alo, Whi + WSLOT, Wlo + WSLOT, w_bih_b,
                                          xpw + (size_t)MW * G3, G3, nullptr);
    }
    // word BiGRU (tensor-core step; emits bf16 planes into Ahi/Alo)
    {
        dim3 g(8, 8, 2);
        gru_mma<<<g, 384, GRUW_SMEM>>>(xpw, w_whh_f, w_whh_b, w_bhh_f, w_bhh_b,
                                       hw, Ahi, Alo, bwc, bws, NSEQW);
    }

    // word attention: score-fused GEMM + reduce
    wsplit(2);
    {
        dim3 g(4, 256);
        gemm_tc<1><<<g, 256, GEMM_SMEM>>>(Ahi, Alo, Whi + 2 * WSLOT, Wlo + 2 * WSLOT,
                                          w_attn_b, scw, 0, w_ctx);
        attn_reduce2<<<NSEQW, 256>>>(scw, Ahi, Alo, sent, LW);
    }

    // sentence input-gate GEMMs
    wsplit(3); wsplit(4);
    conv_split<<<(NSEQW * 128 + 255) / 256, 256>>>((const float4*)sent, Ahi, Alo, NSEQW * 128);
    {
        dim3 g(6, 2);
        gemm_tc<0><<<g, 256, GEMM_SMEM>>>(Ahi, Alo, Whi + 3 * WSLOT, Wlo + 3 * WSLOT,
                                          s_bih_f, xps, G3, nullptr);
        gemm_tc<0><<<g, 256, GEMM_SMEM>>>(Ahi, Alo, Whi + 4 * WSLOT, Wlo + 4 * WSLOT,
                                          s_bih_b, xps + (size_t)BATCH * NSENT * G3, G3, nullptr);
    }

    // sentence BiGRU (emits bf16 planes into Ahi/Alo)
    {
        dim3 g(8, 1, 2);
        gru_reg<NSENT, 16><<<g, 512>>>(xps, s_whh_f, s_whh_b, s_bhh_f, s_bhh_b,
                                       hs, Ahi, Alo, bsc, bss, BATCH);
    }

    // sentence attention -> output
    wsplit(5);
    {
        dim3 g(4, 2);
        gemm_tc<1><<<g, 256, GEMM_SMEM>>>(Ahi, Alo, Whi + 5 * WSLOT, Wlo + 5 * WSLOT,
                                          s_attn_b, scs, 0, s_ctx);
        attn_reduce2<<<BATCH, 256>>>(scs, Ahi, Alo, (float*)d_out, NSENT);
    }
}

// round 17
// speedup vs baseline: 1.8291x; 1.0153x over previous
#include <cuda_runtime.h>
#include <cuda_bf16.h>
#include <math.h>
#include <stdint.h>

#define HID     512
#define HH      256
#define G3      768
#define BATCH   16
#define NSENT   16
#define LW      128
#define NSEQW   256
#define MW      32768
#define WSLOT   (768 * 512)

__device__ float g_xpw[2UL * MW * G3];
__device__ float g_sent[NSEQW * HID];
__device__ float g_xps[2 * BATCH * NSENT * G3];
__device__ float g_scw[MW];
__device__ float g_scs[BATCH * NSENT];
__device__ float g_hw[2 * 2 * HH * NSEQW];
__device__ float g_hs[2 * 2 * HH * BATCH];
__device__ unsigned g_barw_cnt[16], g_barw_sense[16];
__device__ unsigned g_bars_cnt[2],  g_bars_sense[2];
__device__ __nv_bfloat16 g_Ahi[(size_t)MW * HID];
__device__ __nv_bfloat16 g_Alo[(size_t)MW * HID];
__device__ __nv_bfloat16 g_Whi[6 * WSLOT];
__device__ __nv_bfloat16 g_Wlo[6 * WSLOT];

__device__ __forceinline__ uint32_t smem_u32(const void* p) {
    uint32_t a;
    asm("{ .reg .u64 t; cvta.to.shared.u64 t, %1; cvt.u32.u64 %0, t; }" : "=r"(a) : "l"(p));
    return a;
}
__device__ __forceinline__ void ldsm4(uint32_t* r, uint32_t addr) {
    asm volatile("ldmatrix.sync.aligned.m8n8.x4.shared.b16 {%0,%1,%2,%3}, [%4];"
                 : "=r"(r[0]), "=r"(r[1]), "=r"(r[2]), "=r"(r[3]) : "r"(addr));
}
__device__ __forceinline__ void mma_bf16(float* c, const uint32_t* a, const uint32_t* b) {
    asm volatile("mma.sync.aligned.m16n8k16.row.col.f32.bf16.bf16.f32 "
                 "{%0,%1,%2,%3}, {%4,%5,%6,%7}, {%8,%9}, {%0,%1,%2,%3};"
                 : "+f"(c[0]), "+f"(c[1]), "+f"(c[2]), "+f"(c[3])
                 : "r"(a[0]), "r"(a[1]), "r"(a[2]), "r"(a[3]), "r"(b[0]), "r"(b[1]));
}

// fast gate functions (__expf: ~2 ulp; negligible vs bf16x3 4e-5)
__device__ __forceinline__ float fsigmoid(float x) {
    return 1.f / (1.f + __expf(-x));
}
__device__ __forceinline__ float ftanh_(float x) {
    float e = __expf(-2.f * x);
    return (1.f - e) / (1.f + e);
}

__device__ __forceinline__ void split4(float4 v, __nv_bfloat162* h, __nv_bfloat162* l) {
    float x[4] = {v.x, v.y, v.z, v.w};
    __nv_bfloat16 hh[4], ll[4];
#pragma unroll
    for (int i = 0; i < 4; i++) {
        hh[i] = __float2bfloat16_rn(x[i]);
        ll[i] = __float2bfloat16_rn(x[i] - __bfloat162float(hh[i]));
    }
    h[0] = __nv_bfloat162(hh[0], hh[1]); h[1] = __nv_bfloat162(hh[2], hh[3]);
    l[0] = __nv_bfloat162(ll[0], ll[1]); l[1] = __nv_bfloat162(ll[2], ll[3]);
}

__device__ __forceinline__ void split8(float4 a, float4 b, uint4& hi4, uint4& lo4) {
    __nv_bfloat162 h[2], l[2];
    split4(a, h, l);
    hi4.x = *(uint32_t*)&h[0]; hi4.y = *(uint32_t*)&h[1];
    lo4.x = *(uint32_t*)&l[0]; lo4.y = *(uint32_t*)&l[1];
    split4(b, h, l);
    hi4.z = *(uint32_t*)&h[0]; hi4.w = *(uint32_t*)&h[1];
    lo4.z = *(uint32_t*)&l[0]; lo4.w = *(uint32_t*)&l[1];
}

__global__ void conv_split(const float4* __restrict__ src,
                           __nv_bfloat16* __restrict__ hi,
                           __nv_bfloat16* __restrict__ lo, int n4) {
    int i = blockIdx.x * blockDim.x + threadIdx.x;
    if (i >= n4) return;
    __nv_bfloat162 h[2], l[2];
    split4(src[i], h, l);
    ((__nv_bfloat162*)hi)[2 * i] = h[0]; ((__nv_bfloat162*)hi)[2 * i + 1] = h[1];
    ((__nv_bfloat162*)lo)[2 * i] = l[0]; ((__nv_bfloat162*)lo)[2 * i + 1] = l[1];
}

__global__ void conv_split_gather(const float4* __restrict__ tf,
                                  __nv_bfloat16* __restrict__ hi,
                                  __nv_bfloat16* __restrict__ lo) {
    int i = blockIdx.x * blockDim.x + threadIdx.x;
    if (i >= MW * 128) return;
    int m = i >> 7, kq = i & 127;
    float4 v = tf[((size_t)((m & 2047) * 16 + (m >> 11))) * 128 + kq];
    __nv_bfloat162 h[2], l[2];
    split4(v, h, l);
    ((__nv_bfloat162*)hi)[2 * i] = h[0]; ((__nv_bfloat162*)hi)[2 * i + 1] = h[1];
    ((__nv_bfloat162*)lo)[2 * i] = l[0]; ((__nv_bfloat162*)lo)[2 * i + 1] = l[1];
}

__global__ void zero_scores(float* a, int na, float* b, int nb) {
    int i = blockIdx.x * blockDim.x + threadIdx.x;
    if (i < na) a[i] = 0.f;
    if (i < nb) b[i] = 0.f;
}

// MODE 0: C[m][n] = sum_k A[m][k]*B[n][k] + bias[n]
// MODE 1: C[m] += sum_n tanh(acc + bias[n]) * ctx[n]
#define GEMM_SMEM 131072
template<int MODE>
__global__ void __launch_bounds__(256, 1)
gemm_tc(const __nv_bfloat16* __restrict__ Ahi, const __nv_bfloat16* __restrict__ Alo,
        const __nv_bfloat16* __restrict__ Bhi, const __nv_bfloat16* __restrict__ Blo,
        const float* __restrict__ bias, float* __restrict__ C, int ldc,
        const float* __restrict__ ctx)
{
    extern __shared__ __align__(128) char smg[];
    const uint32_t sb = smem_u32(smg);
    const int tid = threadIdx.x;
    const int lane = tid & 31, wid = tid >> 5;
    const int wm = wid >> 2, wn = wid & 3;
    const int m0 = blockIdx.y * 128, n0 = blockIdx.x * 128;

    const __nv_bfloat16* planes[4] = {
        Ahi + (size_t)m0 * 512, Alo + (size_t)m0 * 512,
        Bhi + (size_t)n0 * 512, Blo + (size_t)n0 * 512 };

    const int rb = lane & 7;
    const int glA = lane >> 4;
    const int glB = lane >> 3;
    int aoff[4], boff[4];
#pragma unroll
    for (int mt = 0; mt < 4; mt++) {
        int r = wm * 64 + mt * 16 + rb + ((lane >> 3) & 1) * 8;
        aoff[mt] = ((r >> 3) << 10) + (rb << 7);
    }
#pragma unroll
    for (int nt = 0; nt < 4; nt++) {
        int r = wn * 32 + nt * 8 + rb;
        boff[nt] = ((r >> 3) << 10) + (rb << 7);
    }

    float acc[4][4][4];
#pragma unroll
    for (int a = 0; a < 4; a++)
#pragma unroll
        for (int b = 0; b < 4; b++)
#pragma unroll
            for (int d = 0; d < 4; d++) acc[a][b][d] = 0.f;

    const int ldg = tid & 7;
    const int ldr = tid >> 3;

#pragma unroll
    for (int i = 0; i < 16; i++) {
        const int pl = i >> 2;
        const int r = ((i & 3) << 5) + ldr;
        const __nv_bfloat16* src = planes[pl] + (size_t)r * 512 + ldg * 8;
        uint32_t dst = sb + pl * 16384 + ((r >> 3) << 10) + ((r & 7) << 7)
                       + ((ldg ^ (r & 7)) << 4);
        asm volatile("cp.async.cg.shared.global [%0], [%1], 16;" :: "r"(dst), "l"(src));
    }
    asm volatile("cp.async.commit_group;" ::: "memory");

    for (int c = 0; c < 8; c++) {
        asm volatile("cp.async.wait_group 0;" ::: "memory");
        __syncthreads();
        if (c < 7) {
            const int k0 = (c + 1) << 6;
            const uint32_t dbase = sb + ((c + 1) & 1) * 65536;
#pragma unroll
            for (int i = 0; i < 16; i++) {
                const int pl = i >> 2;
                const int r = ((i & 3) << 5) + ldr;
                const __nv_bfloat16* src = planes[pl] + (size_t)r * 512 + k0 + ldg * 8;
                uint32_t dst = dbase + pl * 16384 + ((r >> 3) << 10) + ((r & 7) << 7)
                               + ((ldg ^ (r & 7)) << 4);
                asm volatile("cp.async.cg.shared.global [%0], [%1], 16;" :: "r"(dst), "l"(src));
            }
            asm volatile("cp.async.commit_group;" ::: "memory");
        }

        const uint32_t bbase = sb + (c & 1) * 65536;
        uint32_t Bf[2][4][4];
#pragma unroll
        for (int s = 0; s < 4; s++) {
            if ((s & 1) == 0) {
                const int q0 = s << 1;
#pragma unroll
                for (int pl = 0; pl < 2; pl++)
#pragma unroll
                    for (int nt = 0; nt < 4; nt++)
                        ldsm4(Bf[pl][nt],
                              bbase + (2 + pl) * 16384 + boff[nt]
                              + (((q0 + glB) ^ rb) << 4));
            }
            uint32_t Af[2][4][4];
#pragma unroll
            for (int pl = 0; pl < 2; pl++)
#pragma unroll
                for (int mt = 0; mt < 4; mt++)
                    ldsm4(Af[pl][mt],
                          bbase + pl * 16384 + aoff[mt]
                          + ((((s << 1) + glA) ^ rb) << 4));
            const int ro = (s & 1) << 1;
#pragma unroll
            for (int mt = 0; mt < 4; mt++)
#pragma unroll
                for (int nt = 0; nt < 4; nt++) {
                    mma_bf16(acc[mt][nt], Af[0][mt], &Bf[0][nt][ro]);
                    mma_bf16(acc[mt][nt], Af[0][mt], &Bf[1][nt][ro]);
                    mma_bf16(acc[mt][nt], Af[1][mt], &Bf[0][nt][ro]);
                }
        }
    }

    const int rr = lane >> 2, cc = (lane & 3) * 2;
    if (MODE == 0) {
#pragma unroll
        for (int mt = 0; mt < 4; mt++) {
            const int row = m0 + wm * 64 + mt * 16 + rr;
#pragma unroll
            for (int nt = 0; nt < 4; nt++) {
                const int col = n0 + wn * 32 + nt * 8 + cc;
                const float b0 = bias[col], b1 = bias[col + 1];
                float2 v0 = {acc[mt][nt][0] + b0, acc[mt][nt][1] + b1};
                float2 v1 = {acc[mt][nt][2] + b0, acc[mt][nt][3] + b1};
                *(float2*)(C + (size_t)row * ldc + col) = v0;
                *(float2*)(C + (size_t)(row + 8) * ldc + col) = v1;
            }
        }
    } else {
#pragma unroll
        for (int mt = 0; mt < 4; mt++) {
            float s0 = 0.f, s1 = 0.f;
#pragma unroll
            for (int nt = 0; nt < 4; nt++) {
                const int col = n0 + wn * 32 + nt * 8 + cc;
                const float b0 = bias[col], b1 = bias[col + 1];
                const float c0 = ctx[col],  c1 = ctx[col + 1];
                s0 += tanhf(acc[mt][nt][0] + b0) * c0 + tanhf(acc[mt][nt][1] + b1) * c1;
                s1 += tanhf(acc[mt][nt][2] + b0) * c0 + tanhf(acc[mt][nt][3] + b1) * c1;
            }
            s0 += __shfl_xor_sync(0xffffffffu, s0, 1);
            s0 += __shfl_xor_sync(0xffffffffu, s0, 2);
            s1 += __shfl_xor_sync(0xffffffffu, s1, 1);
            s1 += __shfl_xor_sync(0xffffffffu, s1, 2);
            if ((lane & 3) == 0) {
                const int row = m0 + wm * 64 + mt * 16 + rr;
                atomicAdd(C + row, s0);
                atomicAdd(C + row + 8, s1);
            }
        }
    }
}

__device__ __forceinline__ unsigned ld_acq(const unsigned* p) {
    unsigned v;
    asm volatile("ld.acquire.gpu.u32 %0, [%1];" : "=r"(v) : "l"(p) : "memory");
    return v;
}
// R14-proven barrier: single atomic + single-word sense spin
__device__ __forceinline__ void group_barrier(unsigned* cnt, unsigned* sense,
                                              unsigned target, int total) {
    __syncthreads();
    if (threadIdx.x == 0) {
        __threadfence();
        unsigned t = atomicAdd(cnt, 1u);
        if (t == (unsigned)(total - 1)) {
            *cnt = 0u;
            asm volatile("red.release.gpu.add.u32 [%0], 1;" :: "l"(sense) : "memory");
        } else {
            while (ld_acq(sense) != target) { }
        }
    }
    __syncthreads();
}

// word GRU on tensor cores: R14 mma phase, fast gates, hold in registers
#define GRUW_SMEM 144128
__global__ void __launch_bounds__(384, 1)
gru_mma(const float* __restrict__ xp_base,
        const float* __restrict__ whh_f, const float* __restrict__ whh_b,
        const float* __restrict__ bhh_f, const float* __restrict__ bhh_b,
        float* __restrict__ hbuf,
        __nv_bfloat16* __restrict__ ohi, __nv_bfloat16* __restrict__ olo,
        unsigned* cnt_arr, unsigned* sense_arr, int nseq)
{
    constexpr int T = LW;
    extern __shared__ __align__(128) char smem[];
    const uint32_t sb = smem_u32(smem);
    const uint32_t WH = 0, WL = 49152, HHp = 98304, HLp = 114688;
    float* Csm = (float*)(smem + 131072);
    float* bsm = (float*)(smem + 143744);

    const int tid = threadIdx.x;
    const int lane = tid & 31, wid = tid >> 5;
    const int j0 = blockIdx.x * 32;
    const int sg0 = blockIdx.y * 32;
    const int dir = blockIdx.z;
    const int gidx = dir * gridDim.y + blockIdx.y;
    unsigned* bcnt = cnt_arr + gidx;
    unsigned* bsense = sense_arr + gidx;
    const float* whh = dir ? whh_b : whh_f;
    const float* bhh = dir ? bhh_b : bhh_f;
    const float* xp  = xp_base + (size_t)dir * nseq * T * G3;

    for (int task = tid; task < 96 * 32; task += 384) {
        int row = task >> 5, c = task & 31;
        int grow = (row >> 5) * 256 + j0 + (row & 31);
        const float* src = whh + (size_t)grow * 256 + c * 8;
        float4 v0 = *(const float4*)src;
        float4 v1 = *(const float4*)(src + 4);
        uint4 hi4, lo4;
        split8(v0, v1, hi4, lo4);
        uint32_t off = row * 512 + ((c ^ (row & 7)) << 4);
        *(uint4*)(smem + WH + off) = hi4;
        *(uint4*)(smem + WL + off) = lo4;
    }
    for (int i = tid; i < 96; i += 384)
        bsm[i] = bhh[(i >> 5) * 256 + j0 + (i & 31)];

    const unsigned base = ld_acq(bsense);
    const int wm = wid >> 1;
    const int np = wid & 1;
    const int rb = lane & 7;
    const int glA = lane >> 4;
    const int glB = lane >> 3;
    const uint32_t arow = (uint32_t)(wm * 16 + rb + ((lane >> 3) & 1) * 8) * 512;
    const int rr = lane >> 2, cc = (lane & 3) * 2;

    float xr_[3], xz_[3], xn_[3];
    float hreg[3] = {0.f, 0.f, 0.f};     // hold for (seq, jj) owned by pair p
    {
        const int tt0 = dir ? (T - 1) : 0;
#pragma unroll
        for (int k = 0; k < 3; k++) {
            int p = tid + k * 384;
            if (p < 1024) {
                int seq = p >> 5, jj = p & 31;
                const float* row = xp + ((size_t)(sg0 + seq) * T + tt0) * G3;
                xr_[k] = row[j0 + jj];
                xz_[k] = row[256 + j0 + jj];
                xn_[k] = row[512 + j0 + jj];
            }
        }
    }
    __syncthreads();

    for (int step = 0; step < T; step++) {
        const int tt = dir ? (T - 1 - step) : step;

        // phase 1: stage/convert h(t) (bf16 planes only; hold is in registers)
        if (step == 0) {
            for (int e = tid; e < 2048; e += 384)
                *(uint4*)(smem + HHp + e * 16) = make_uint4(0, 0, 0, 0);
        } else {
            const float* hcur = hbuf + ((size_t)((step & 1) * 2 + dir)) * nseq * 256
                                + (size_t)sg0 * 256;
            for (int task = tid; task < 1024; task += 384) {
                int row = task >> 5, c = task & 31;
                const float* src = hcur + row * 256 + c * 8;
                float4 v0 = *(const float4*)src;
                float4 v1 = *(const float4*)(src + 4);
                uint4 hi4, lo4;
                split8(v0, v1, hi4, lo4);
                uint32_t off = row * 512 + ((c ^ (row & 7)) << 4);
                *(uint4*)(smem + HHp + off) = hi4;
                *(uint4*)(smem + HLp + off) = lo4;
            }
        }
        __syncthreads();

        // phase 2: mma C[96 x 32] = W * h^T (bf16x3, single accumulator)
        {
            float acc[2][4];
#pragma unroll
            for (int t = 0; t < 2; t++)
#pragma unroll
                for (int d = 0; d < 4; d++) acc[t][d] = 0.f;
            uint32_t Bf[2][2][4];
#pragma unroll
            for (int s = 0; s < 16; s++) {
                if ((s & 1) == 0) {
                    const int q0 = s << 1;
#pragma unroll
                    for (int pl = 0; pl < 2; pl++)
#pragma unroll
                        for (int t = 0; t < 2; t++) {
                            uint32_t brow = (uint32_t)((np * 2 + t) * 8 + rb) * 512;
                            ldsm4(Bf[pl][t], sb + (pl ? HLp : HHp) + brow
                                  + (((q0 + glB) ^ rb) << 4));
                        }
                }
                uint32_t Af[2][4];
#pragma unroll
                for (int pl = 0; pl < 2; pl++)
                    ldsm4(Af[pl], sb + (pl ? WL : WH) + arow
                          + ((((s << 1) + glA) ^ rb) << 4));
                const int ro = (s & 1) << 1;
#pragma unroll
                for (int t = 0; t < 2; t++) {
                    mma_bf16(acc[t], Af[0], &Bf[0][t][ro]);
                    mma_bf16(acc[t], Af[0], &Bf[1][t][ro]);
                    mma_bf16(acc[t], Af[1], &Bf[0][t][ro]);
                }
            }
            const int row = wm * 16 + rr;
#pragma unroll
            for (int t = 0; t < 2; t++) {
                const int col = (np * 2 + t) * 8 + cc;
                Csm[row * 33 + col]           = acc[t][0];
                Csm[row * 33 + col + 1]       = acc[t][1];
                Csm[(row + 8) * 33 + col]     = acc[t][2];
                Csm[(row + 8) * 33 + col + 1] = acc[t][3];
            }
        }
        __syncthreads();

        // phase 3: fast gates; hold from registers; store h(t+1) + bf16 planes
        float* hnext = hbuf + ((size_t)(((step + 1) & 1) * 2 + dir)) * nseq * 256
                       + (size_t)sg0 * 256;
        const bool notlast = (step < T - 1);
#pragma unroll
        for (int k = 0; k < 3; k++) {
            int p = tid + k * 384;
            if (p < 1024) {
                int seq = p >> 5, jj = p & 31;
                float sR = Csm[jj * 33 + seq];
                float sZ = Csm[(32 + jj) * 33 + seq];
                float sN = Csm[(64 + jj) * 33 + seq];
                float r  = fsigmoid(xr_[k] + sR + bsm[jj]);
                float z  = fsigmoid(xz_[k] + sZ + bsm[32 + jj]);
                float nn = ftanh_(xn_[k] + r * (sN + bsm[64 + jj]));
                float hnew = (1.f - z) * nn + z * hreg[k];
                hreg[k] = hnew;
                if (notlast) hnext[seq * 256 + j0 + jj] = hnew;
                size_t oidx = ((size_t)(sg0 + seq) * T + tt) * HID + dir * HH + j0 + jj;
                __nv_bfloat16 hb = __float2bfloat16_rn(hnew);
                ohi[oidx] = hb;
                olo[oidx] = __float2bfloat16_rn(hnew - __bfloat162float(hb));
            }
        }

        if (notlast) {
            const int t2 = dir ? (T - 2 - step) : (step + 1);
#pragma unroll
            for (int k = 0; k < 3; k++) {
                int p = tid + k * 384;
                if (p < 1024) {
                    int seq = p >> 5, jj = p & 31;
                    const float* row = xp + ((size_t)(sg0 + seq) * T + t2) * G3;
                    xr_[k] = row[j0 + jj];
                    xz_[k] = row[256 + j0 + jj];
                    xn_[k] = row[512 + j0 + jj];
                }
            }
            group_barrier(bcnt, bsense, base + (unsigned)step + 1u, 8);
        }
    }
}

// sentence GRU: R8 butterfly + fast gates + hold in registers
template<int T, int SPB>
__global__ void __launch_bounds__(512, 1)
gru_reg(const float* __restrict__ xp_base,
        const float* __restrict__ whh_f, const float* __restrict__ whh_b,
        const float* __restrict__ bhh_f, const float* __restrict__ bhh_b,
        float* __restrict__ hbuf,
        __nv_bfloat16* __restrict__ ohi, __nv_bfloat16* __restrict__ olo,
        unsigned* cnt_arr, unsigned* sense_arr, int nseq)
{
    constexpr int NQ = SPB / 8;
    constexpr int HROW = 320;
    __shared__ __align__(16) float hsm[SPB * HROW];
    __shared__ float xs[32 * (SPB + 1)];

    const int tid = threadIdx.x;
    const int jj = tid >> 4;
    const int ks = tid & 15;
    const int j0 = blockIdx.x * 32;
    const int sg0 = blockIdx.y * SPB;
    const int dir = blockIdx.z;
    const int gidx = blockIdx.z * gridDim.y + blockIdx.y;
    unsigned* bcnt = cnt_arr + gidx;
    unsigned* bsense = sense_arr + gidx;
    const float* whh = dir ? whh_b : whh_f;
    const float* bhh = dir ? bhh_b : bhh_f;
    const float* xp  = xp_base + (size_t)dir * nseq * T * G3;
    const int j = j0 + jj;

    unsigned long long Wp[3][8];
#pragma unroll
    for (int g = 0; g < 3; g++)
#pragma unroll
        for (int p = 0; p < 4; p++) {
            float4 v = *(const float4*)(whh + ((size_t)(g * 256 + j)) * 256
                                        + ks * 16 + p * 4);
            asm("mov.b64 %0, {%1,%2};" : "=l"(Wp[g][2*p])     : "f"(v.x), "f"(v.y));
            asm("mov.b64 %0, {%1,%2};" : "=l"(Wp[g][2*p + 1]) : "f"(v.z), "f"(v.w));
        }

    const float br = bhh[j], bz = bhh[256 + j], bn = bhh[512 + j];
    const uint32_t hbase = smem_u32(hsm);
    const unsigned base = ld_acq(bsense);
    const bool own = (ks < 8);
    const bool b0 = (ks & 1), b1 = ((ks >> 1) & 1), b2 = ((ks >> 2) & 1);

    float xr_[NQ], xz_[NQ], xn_[NQ];
    float holdr[NQ];
#pragma unroll
    for (int q = 0; q < NQ; q++) holdr[q] = 0.f;
    if (own) {
        const int tt = dir ? (T - 1) : 0;
#pragma unroll
        for (int q = 0; q < NQ; q++) {
            const float* row = xp + ((size_t)(sg0 + q * 8 + ks) * T + tt) * G3;
            xr_[q] = row[j]; xz_[q] = row[256 + j]; xn_[q] = row[512 + j];
        }
    }

    for (int step = 0; step < T; step++) {
        const int tt = dir ? (T - 1 - step) : step;

        if (step == 0) {
            for (int e = tid; e < SPB * HROW; e += 512) hsm[e] = 0.f;
        } else {
            const float4* hcur4 = (const float4*)(hbuf
                + ((size_t)((step & 1) * 2 + dir)) * nseq * 256 + (size_t)sg0 * 256);
#pragma unroll
            for (int i = 0; i < SPB / 8; i++) {
                int e = tid + i * 512;
                int s = e >> 6, c4 = e & 63;
                float4 v = hcur4[e];
                *(float4*)(hsm + s * HROW + (c4 >> 2) * 20 + (c4 & 3) * 4) = v;
            }
        }
        __syncthreads();

#pragma unroll
        for (int q = 0; q < NQ; q++) {
            float v3[3][8];
#pragma unroll
            for (int s8 = 0; s8 < 8; s8++) {
                const int s = q * 8 + s8;
                const uint32_t ha = hbase + (uint32_t)(s * HROW) * 4 + ks * 80;
                unsigned long long a0 = 0ULL, a1 = 0ULL, a2 = 0ULL;
#pragma unroll
                for (int p = 0; p < 4; p++) {
                    unsigned long long h0, h1;
                    asm("ld.shared.v2.b64 {%0,%1}, [%2];"
                        : "=l"(h0), "=l"(h1) : "r"(ha + p * 16));
                    asm("fma.rn.f32x2 %0, %1, %2, %0;" : "+l"(a0) : "l"(Wp[0][2*p]),   "l"(h0));
                    asm("fma.rn.f32x2 %0, %1, %2, %0;" : "+l"(a1) : "l"(Wp[1][2*p]),   "l"(h0));
                    asm("fma.rn.f32x2 %0, %1, %2, %0;" : "+l"(a2) : "l"(Wp[2][2*p]),   "l"(h0));
                    asm("fma.rn.f32x2 %0, %1, %2, %0;" : "+l"(a0) : "l"(Wp[0][2*p+1]), "l"(h1));
                    asm("fma.rn.f32x2 %0, %1, %2, %0;" : "+l"(a1) : "l"(Wp[1][2*p+1]), "l"(h1));
                    asm("fma.rn.f32x2 %0, %1, %2, %0;" : "+l"(a2) : "l"(Wp[2][2*p+1]), "l"(h1));
                }
                float lo, hi;
                asm("mov.b64 {%0,%1}, %2;" : "=f"(lo), "=f"(hi) : "l"(a0)); v3[0][s8] = lo + hi;
                asm("mov.b64 {%0,%1}, %2;" : "=f"(lo), "=f"(hi) : "l"(a1)); v3[1][s8] = lo + hi;
                asm("mov.b64 {%0,%1}, %2;" : "=f"(lo), "=f"(hi) : "l"(a2)); v3[2][s8] = lo + hi;
            }

            float sv[3];
#pragma unroll
            for (int g = 0; g < 3; g++) {
                float t0[4], t1[2];
#pragma unroll
                for (int i = 0; i < 4; i++) {
                    float keep = b0 ? v3[g][2*i + 1] : v3[g][2*i];
                    float send = b0 ? v3[g][2*i]     : v3[g][2*i + 1];
                    t0[i] = keep + __shfl_xor_sync(0xffffffffu, send, 1);
                }
#pragma unroll
                for (int i = 0; i < 2; i++) {
                    float keep = b1 ? t0[2*i + 1] : t0[2*i];
                    float send = b1 ? t0[2*i]     : t0[2*i + 1];
                    t1[i] = keep + __shfl_xor_sync(0xffffffffu, send, 2);
                }
                float keep = b2 ? t1[1] : t1[0];
                float send = b2 ? t1[0] : t1[1];
                float r = keep + __shfl_xor_sync(0xffffffffu, send, 4);
                r += __shfl_xor_sync(0xffffffffu, r, 8);
                sv[g] = r;
            }

            if (own) {
                const int s = q * 8 + ks;
                const float r  = fsigmoid(xr_[q] + sv[0] + br);
                const float z  = fsigmoid(xz_[q] + sv[1] + bz);
                const float nn = ftanh_(xn_[q] + r * (sv[2] + bn));
                const float hnew = (1.f - z) * nn + z * holdr[q];
                holdr[q] = hnew;
                xs[jj * (SPB + 1) + s] = hnew;
                size_t oidx = ((size_t)(sg0 + s) * T + tt) * HID + dir * HH + j;
                __nv_bfloat16 hb = __float2bfloat16_rn(hnew);
                ohi[oidx] = hb;
                olo[oidx] = __float2bfloat16_rn(hnew - __bfloat162float(hb));
            }
        }
        __syncthreads();

        if (step < T - 1) {
            float* hnext = hbuf + ((size_t)(((step + 1) & 1) * 2 + dir)) * nseq * 256
                           + (size_t)sg0 * 256;
#pragma unroll
            for (int e = tid; e < SPB * 32; e += 512) {
                int s = e >> 5, jr = e & 31;
                hnext[s * 256 + j0 + jr] = xs[jr * (SPB + 1) + s];
            }
            const int t2 = dir ? (T - 2 - step) : (step + 1);
            if (own) {
#pragma unroll
                for (int q = 0; q < NQ; q++) {
                    const float* row = xp + ((size_t)(sg0 + q * 8 + ks) * T + t2) * G3;
                    xr_[q] = row[j]; xz_[q] = row[256 + j]; xn_[q] = row[512 + j];
                }
            }
            group_barrier(bcnt, bsense, base + (unsigned)step + 1u, 8);
        }
    }
}

// attention reduce from scores; feats reconstructed from bf16 hi/lo planes
__global__ __launch_bounds__(256)
void attn_reduce2(const float* __restrict__ scores,
                  const __nv_bfloat16* __restrict__ fhi,
                  const __nv_bfloat16* __restrict__ flo,
                  float* __restrict__ dst,
                  int T)
{
    const int seq = blockIdx.x;
    const int tid = threadIdx.x;
    __shared__ float ssc[128];
    __shared__ float sred[256];

    float v = (tid < T) ? scores[seq * T + tid] : -1e30f;
    sred[tid] = v; __syncthreads();
    for (int o = 128; o; o >>= 1) { if (tid < o) sred[tid] = fmaxf(sred[tid], sred[tid + o]); __syncthreads(); }
    float mx = sred[0]; __syncthreads();
    float e = (tid < T) ? expf(v - mx) : 0.f;
    sred[tid] = e; __syncthreads();
    for (int o = 128; o; o >>= 1) { if (tid < o) sred[tid] += sred[tid + o]; __syncthreads(); }
    float inv = 1.f / sred[0]; __syncthreads();
    if (tid < T) ssc[tid] = e * inv;
    __syncthreads();

    const __nv_bfloat162* h2 = (const __nv_bfloat162*)fhi;
    const __nv_bfloat162* l2 = (const __nv_bfloat162*)flo;
    float a0 = 0.f, a1 = 0.f;
    for (int t = 0; t < T; t++) {
        const size_t base2 = ((size_t)seq * T + t) * 256 + tid;
        __nv_bfloat162 hv = h2[base2];
        __nv_bfloat162 lv = l2[base2];
        float w = ssc[t];
        a0 = fmaf(w, __bfloat162float(hv.x) + __bfloat162float(lv.x), a0);
        a1 = fmaf(w, __bfloat162float(hv.y) + __bfloat162float(lv.y), a1);
    }
    dst[(size_t)seq * 512 + 2 * tid]     = a0;
    dst[(size_t)seq * 512 + 2 * tid + 1] = a1;
}

extern "C" void kernel_launch(void* const* d_in, const int* in_sizes, int n_in,
                              void* d_out, int out_size)
{
    const float* tf       = (const float*)d_in[0];
    const float* w_wih_f  = (const float*)d_in[2];
    const float* w_whh_f  = (const float*)d_in[3];
    const float* w_bih_f  = (const float*)d_in[4];
    const float* w_bhh_f  = (const float*)d_in[5];
    const float* w_wih_b  = (const float*)d_in[6];
    const float* w_whh_b  = (const float*)d_in[7];
    const float* w_bih_b  = (const float*)d_in[8];
    const float* w_bhh_b  = (const float*)d_in[9];
    const float* s_wih_f  = (const float*)d_in[10];
    const float* s_whh_f  = (const float*)d_in[11];
    const float* s_bih_f  = (const float*)d_in[12];
    const float* s_bhh_f  = (const float*)d_in[13];
    const float* s_wih_b  = (const float*)d_in[14];
    const float* s_whh_b  = (const float*)d_in[15];
    const float* s_bih_b  = (const float*)d_in[16];
    const float* s_bhh_b  = (const float*)d_in[17];
    const float* w_attn_w = (const float*)d_in[18];
    const float* w_attn_b = (const float*)d_in[19];
    const float* w_ctx    = (const float*)d_in[20];
    const float* s_attn_w = (const float*)d_in[21];
    const float* s_attn_b = (const float*)d_in[22];
    const float* s_ctx    = (const float*)d_in[23];

    float *xpw, *sent, *xps, *hw, *hs, *scw, *scs;
    unsigned *bwc, *bws, *bsc, *bss;
    __nv_bfloat16 *Ahi, *Alo, *Whi, *Wlo;
    cudaGetSymbolAddress((void**)&xpw,  g_xpw);
    cudaGetSymbolAddress((void**)&sent, g_sent);
    cudaGetSymbolAddress((void**)&xps,  g_xps);
    cudaGetSymbolAddress((void**)&scw,  g_scw);
    cudaGetSymbolAddress((void**)&scs,  g_scs);
    cudaGetSymbolAddress((void**)&hw,   g_hw);
    cudaGetSymbolAddress((void**)&hs,   g_hs);
    cudaGetSymbolAddress((void**)&bwc,  g_barw_cnt);
    cudaGetSymbolAddress((void**)&bws,  g_barw_sense);
    cudaGetSymbolAddress((void**)&bsc,  g_bars_cnt);
    cudaGetSymbolAddress((void**)&bss,  g_bars_sense);
    cudaGetSymbolAddress((void**)&Ahi,  g_Ahi);
    cudaGetSymbolAddress((void**)&Alo,  g_Alo);
    cudaGetSymbolAddress((void**)&Whi,  g_Whi);
    cudaGetSymbolAddress((void**)&Wlo,  g_Wlo);

    cudaFuncSetAttribute(gemm_tc<0>,
                         cudaFuncAttributeMaxDynamicSharedMemorySize, GEMM_SMEM);
    cudaFuncSetAttribute(gemm_tc<1>,
                         cudaFuncAttributeMaxDynamicSharedMemorySize, GEMM_SMEM);
    cudaFuncSetAttribute(gru_mma,
                         cudaFuncAttributeMaxDynamicSharedMemorySize, GRUW_SMEM);

    const float* wsrc[6] = {w_wih_f, w_wih_b, w_attn_w, s_wih_f, s_wih_b, s_attn_w};
    const int    wrows[6] = {768, 768, 512, 768, 768, 512};
    auto wsplit = [&](int i) {
        int n4 = wrows[i] * 128;
        conv_split<<<(n4 + 255) / 256, 256>>>((const float4*)wsrc[i],
                                              Whi + (size_t)i * WSLOT,
                                              Wlo + (size_t)i * WSLOT, n4);
    };

    zero_scores<<<(MW + 255) / 256, 256>>>(scw, MW, scs, BATCH * NSENT);

    wsplit(0); wsplit(1);
    conv_split_gather<<<(MW * 128 + 255) / 256, 256>>>((const float4*)tf, Ahi, Alo);
    {
        dim3 g(6, 256);
        gemm_tc<0><<<g, 256, GEMM_SMEM>>>(Ahi, Alo, Whi, Wlo, w_bih_f, xpw, G3, nullptr);
        gemm_tc<0><<<g, 256, GEMM_SMEM>>>(Ahi, Alo, Whi + WSLOT, Wlo + WSLOT, w_bih_b,
                                          xpw + (size_t)MW * G3, G3, nullptr);
    }
    // word BiGRU (tensor-core step; emits bf16 planes into Ahi/Alo)
    {
        dim3 g(8, 8, 2);
        gru_mma<<<g, 384, GRUW_SMEM>>>(xpw, w_whh_f, w_whh_b, w_bhh_f, w_bhh_b,
                                       hw, Ahi, Alo, bwc, bws, NSEQW);
    }

    // word attention: score-fused GEMM + reduce
    wsplit(2);
    {
        dim3 g(4, 256);
        gemm_tc<1><<<g, 256, GEMM_SMEM>>>(Ahi, Alo, Whi + 2 * WSLOT, Wlo + 2 * WSLOT,
                                          w_attn_b, scw, 0, w_ctx);
        attn_reduce2<<<NSEQW, 256>>>(scw, Ahi, Alo, sent, LW);
    }

    // sentence input-gate GEMMs
    wsplit(3); wsplit(4);
    conv_split<<<(NSEQW * 128 + 255) / 256, 256>>>((const float4*)sent, Ahi, Alo, NSEQW * 128);
    {
        dim3 g(6, 2);
        gemm_tc<0><<<g, 256, GEMM_SMEM>>>(Ahi, Alo, Whi + 3 * WSLOT, Wlo + 3 * WSLOT,
                                          s_bih_f, xps, G3, nullptr);
        gemm_tc<0><<<g, 256, GEMM_SMEM>>>(Ahi, Alo, Whi + 4 * WSLOT, Wlo + 4 * WSLOT,
                                          s_bih_b, xps + (size_t)BATCH * NSENT * G3, G3, nullptr);
    }

    // sentence BiGRU (emits bf16 planes into Ahi/Alo)
    {
        dim3 g(8, 1, 2);
        gru_reg<NSENT, 16><<<g, 512>>>(xps, s_whh_f, s_whh_b, s_bhh_f, s_bhh_b,
                                       hs, Ahi, Alo, bsc, bss, BATCH);
    }

    // sentence attention -> output
    wsplit(5);
    {
        dim3 g(4, 2);
        gemm_tc<1><<<g, 256, GEMM_SMEM>>>(Ahi, Alo, Whi + 5 * WSLOT, Wlo + 5 * WSLOT,
                                          s_attn_b, scs, 0, s_ctx);
        attn_reduce2<<<BATCH, 256>>>(scs, Ahi, Alo, (float*)d_out, NSENT);
    }
}